// round 12
// baseline (speedup 1.0000x reference)
#include <cuda_runtime.h>
#include <cuda_bf16.h>
#include <cstdint>

#define NB 4
#define C 128
#define HW 4096
#define EPSF 1e-7f
#define NTILES (HW / 128)
#define SMS 136      // padded shared stride (uint32 units)
#define KSPLIT 4

// ---------------- scratch ----------------
__device__ __align__(128) float g_k [NB][HW][C];    // K[l][c]
__device__ __align__(128) float g_y [NB][C][HW];    // boxsum [c][p]
__device__ __align__(128) float g_S [NB][HW][HW];   // S[l][p]
__device__ __align__(128) float g_part[KSPLIT][NB][C][HW];  // gemm2 split-K partials
__device__ float g_pm[NTILES][NB][HW];
__device__ float g_ps[NTILES][NB][HW];
__device__ float g_cmax[NB][HW];
__device__ float g_crcp[NB][HW];

// ---------------- helpers (proven) ----------------
__device__ __forceinline__ void bf_split2(float v0, float v1, uint32_t& h, uint32_t& l) {
    __nv_bfloat16 h0 = __float2bfloat16(v0);
    __nv_bfloat16 h1 = __float2bfloat16(v1);
    __nv_bfloat16 l0 = __float2bfloat16(v0 - __bfloat162float(h0));
    __nv_bfloat16 l1 = __float2bfloat16(v1 - __bfloat162float(h1));
    h = (uint32_t)__bfloat16_as_ushort(h0) | ((uint32_t)__bfloat16_as_ushort(h1) << 16);
    l = (uint32_t)__bfloat16_as_ushort(l0) | ((uint32_t)__bfloat16_as_ushort(l1) << 16);
}
__device__ __forceinline__ void mma16(float* c, const uint32_t* a, const uint32_t* b) {
    asm volatile("mma.sync.aligned.m16n8k16.row.col.f32.bf16.bf16.f32 "
        "{%0,%1,%2,%3},{%4,%5,%6,%7},{%8,%9},{%0,%1,%2,%3};"
        : "+f"(c[0]), "+f"(c[1]), "+f"(c[2]), "+f"(c[3])
        : "r"(a[0]), "r"(a[1]), "r"(a[2]), "r"(a[3]), "r"(b[0]), "r"(b[1]));
}

// one BK=16 stage of 3-term split-bf16 mma (proven fragment mapping, kk2=0 only)
__device__ __forceinline__ void mma_block(const uint32_t* pAh, const uint32_t* pAl,
                                          const uint32_t* pBh, const uint32_t* pBl,
                                          int wm, int wn, int gid, int tig,
                                          float acc[4][4][4]) {
    uint32_t ah[4][4], al[4][4], bh[4][2], bl[4][2];
    #pragma unroll
    for (int mf = 0; mf < 4; mf++) {
        int m = wm + mf * 16 + gid;
        ah[mf][0] = pAh[tig * SMS + m];
        ah[mf][1] = pAh[tig * SMS + m + 8];
        ah[mf][2] = pAh[(tig + 4) * SMS + m];
        ah[mf][3] = pAh[(tig + 4) * SMS + m + 8];
        al[mf][0] = pAl[tig * SMS + m];
        al[mf][1] = pAl[tig * SMS + m + 8];
        al[mf][2] = pAl[(tig + 4) * SMS + m];
        al[mf][3] = pAl[(tig + 4) * SMS + m + 8];
    }
    #pragma unroll
    for (int nf = 0; nf < 4; nf++) {
        int n = wn + nf * 8 + gid;
        bh[nf][0] = pBh[tig * SMS + n];
        bh[nf][1] = pBh[(tig + 4) * SMS + n];
        bl[nf][0] = pBl[tig * SMS + n];
        bl[nf][1] = pBl[(tig + 4) * SMS + n];
    }
    #pragma unroll
    for (int mf = 0; mf < 4; mf++)
        #pragma unroll
        for (int nf = 0; nf < 4; nf++) {
            mma16(acc[mf][nf], ah[mf], bl[nf]);
            mma16(acc[mf][nf], al[mf], bh[nf]);
            mma16(acc[mf][nf], ah[mf], bh[nf]);
        }
}

// ---------------------------------------------------------------------------
// prep (proven)
// ---------------------------------------------------------------------------
__global__ void k_prep(const float* __restrict__ fg) {
    int l = blockIdx.x, b = blockIdx.y, c = threadIdx.x;
    float v = fg[((b * C + c) * HW) + l] + EPSF;
    float s = v * v;
    #pragma unroll
    for (int o = 16; o > 0; o >>= 1) s += __shfl_xor_sync(0xffffffffu, s, o);
    __shared__ float ws[4];
    if ((c & 31) == 0) ws[c >> 5] = s;
    __syncthreads();
    float tot = ws[0] + ws[1] + ws[2] + ws[3];
    g_k[b][l][c] = v * rsqrtf(tot);
}

__global__ void y_prep(const float* __restrict__ fg) {
    int idx = blockIdx.x * blockDim.x + threadIdx.x;
    int p = idx & (HW - 1);
    int bc = idx >> 12;
    int i = p >> 6, j = p & 63;
    const float* base = fg + (size_t)bc * HW;
    float s = 0.f;
    #pragma unroll
    for (int di = -1; di <= 1; di++) {
        int ii = i + di;
        if (ii < 0 || ii >= 64) continue;
        #pragma unroll
        for (int dj = -1; dj <= 1; dj++) {
            int jj = j + dj;
            if (jj < 0 || jj >= 64) continue;
            s += base[ii * 64 + jj];
        }
    }
    ((float*)g_y)[idx] = s;
}

// ---------------------------------------------------------------------------
// gemm1: S[l][p] = K[l][:] . Y[:,p]  + partial stats
// double-buffered BK=16, 8 chunks, one sync per chunk
// ---------------------------------------------------------------------------
__global__ __launch_bounds__(256) void gemm1_mma() {
    __shared__ uint32_t sh[2][4][8 * SMS];   // [stage][Ah,Al,Bh,Bl][k2*SMS+col]
    __shared__ float pm_sh[2][128], ps_sh[2][128];

    int b = blockIdx.z, lt = blockIdx.y;
    int l0 = lt * 128, p0 = blockIdx.x * 128;
    int tid = threadIdx.x, wid = tid >> 5, lane = tid & 31;
    int gid = lane >> 2, tig = lane & 3;
    int wm = (wid & 1) * 64, wn = (wid >> 1) * 32;

    const float* Ag = &g_k[b][l0][0];   // rows = m (l), cols = k (c)
    const float* Bg = &g_y[b][0][p0];   // rows = k (c), cols = n (p)

    int am = tid & 127, ah4 = (tid >> 7) * 4;   // A: row am, pairs [ah4, ah4+4)
    int pr = tid >> 5,  bn = (tid & 31) * 4;    // B: pair-row pr, n [bn, bn+4)

    float4 a0, a1, b0, b1;
    a0 = *(const float4*)(Ag + am * C + ah4 * 2);
    a1 = *(const float4*)(Ag + am * C + ah4 * 2 + 4);
    b0 = *(const float4*)(Bg + (size_t)(2 * pr) * HW + bn);
    b1 = *(const float4*)(Bg + (size_t)(2 * pr + 1) * HW + bn);
    {
        uint32_t h, l;
        bf_split2(a0.x, a0.y, h, l); sh[0][0][(ah4+0)*SMS+am] = h; sh[0][1][(ah4+0)*SMS+am] = l;
        bf_split2(a0.z, a0.w, h, l); sh[0][0][(ah4+1)*SMS+am] = h; sh[0][1][(ah4+1)*SMS+am] = l;
        bf_split2(a1.x, a1.y, h, l); sh[0][0][(ah4+2)*SMS+am] = h; sh[0][1][(ah4+2)*SMS+am] = l;
        bf_split2(a1.z, a1.w, h, l); sh[0][0][(ah4+3)*SMS+am] = h; sh[0][1][(ah4+3)*SMS+am] = l;
        uint4 uh, ul;
        bf_split2(b0.x, b1.x, uh.x, ul.x);
        bf_split2(b0.y, b1.y, uh.y, ul.y);
        bf_split2(b0.z, b1.z, uh.z, ul.z);
        bf_split2(b0.w, b1.w, uh.w, ul.w);
        *(uint4*)&sh[0][2][pr*SMS+bn] = uh;
        *(uint4*)&sh[0][3][pr*SMS+bn] = ul;
    }
    __syncthreads();

    float acc[4][4][4] = {};
    for (int it = 0; it < 8; it++) {
        int st = it & 1;
        if (it < 7) {
            int c0 = (it + 1) * 16;
            a0 = *(const float4*)(Ag + am * C + c0 + ah4 * 2);
            a1 = *(const float4*)(Ag + am * C + c0 + ah4 * 2 + 4);
            b0 = *(const float4*)(Bg + (size_t)(c0 + 2 * pr) * HW + bn);
            b1 = *(const float4*)(Bg + (size_t)(c0 + 2 * pr + 1) * HW + bn);
        }
        mma_block(sh[st][0], sh[st][1], sh[st][2], sh[st][3], wm, wn, gid, tig, acc);
        if (it < 7) {
            int ns = st ^ 1;
            uint32_t h, l;
            bf_split2(a0.x, a0.y, h, l); sh[ns][0][(ah4+0)*SMS+am] = h; sh[ns][1][(ah4+0)*SMS+am] = l;
            bf_split2(a0.z, a0.w, h, l); sh[ns][0][(ah4+1)*SMS+am] = h; sh[ns][1][(ah4+1)*SMS+am] = l;
            bf_split2(a1.x, a1.y, h, l); sh[ns][0][(ah4+2)*SMS+am] = h; sh[ns][1][(ah4+2)*SMS+am] = l;
            bf_split2(a1.z, a1.w, h, l); sh[ns][0][(ah4+3)*SMS+am] = h; sh[ns][1][(ah4+3)*SMS+am] = l;
            uint4 uh, ul;
            bf_split2(b0.x, b1.x, uh.x, ul.x);
            bf_split2(b0.y, b1.y, uh.y, ul.y);
            bf_split2(b0.z, b1.z, uh.z, ul.z);
            bf_split2(b0.w, b1.w, uh.w, ul.w);
            *(uint4*)&sh[ns][2][pr*SMS+bn] = uh;
            *(uint4*)&sh[ns][3][pr*SMS+bn] = ul;
            __syncthreads();
        }
    }

    // ---- partial softmax stats (proven) ----
    #pragma unroll
    for (int nf = 0; nf < 4; nf++) {
        #pragma unroll
        for (int h = 0; h < 2; h++) {
            float mx = -1e30f;
            #pragma unroll
            for (int mf = 0; mf < 4; mf++)
                mx = fmaxf(mx, fmaxf(acc[mf][nf][h], acc[mf][nf][2 + h]));
            float sum = 0.f;
            #pragma unroll
            for (int mf = 0; mf < 4; mf++)
                sum += __expf(acc[mf][nf][h] - mx) + __expf(acc[mf][nf][2 + h] - mx);
            #pragma unroll
            for (int off = 4; off < 32; off <<= 1) {
                float mo = __shfl_xor_sync(0xffffffffu, mx, off);
                float so = __shfl_xor_sync(0xffffffffu, sum, off);
                float mn = fmaxf(mx, mo);
                sum = sum * __expf(mx - mn) + so * __expf(mo - mn);
                mx = mn;
            }
            if (gid == 0) {
                int col = wn + nf * 8 + 2 * tig + h;
                pm_sh[wid & 1][col] = mx;
                ps_sh[wid & 1][col] = sum;
            }
        }
    }
    __syncthreads();
    if (tid < 128) {
        float m0 = pm_sh[0][tid], m1 = pm_sh[1][tid];
        float mn = fmaxf(m0, m1);
        float s = ps_sh[0][tid] * __expf(m0 - mn) + ps_sh[1][tid] * __expf(m1 - mn);
        g_pm[lt][b][p0 + tid] = mn;
        g_ps[lt][b][p0 + tid] = s;
    }

    // ---- store S tile (proven) ----
    #pragma unroll
    for (int mf = 0; mf < 4; mf++) {
        #pragma unroll
        for (int nf = 0; nf < 4; nf++) {
            int r = l0 + wm + mf * 16 + gid;
            int cc = p0 + wn + nf * 8 + 2 * tig;
            *(float2*)&g_S[b][r][cc]     = make_float2(acc[mf][nf][0], acc[mf][nf][1]);
            *(float2*)&g_S[b][r + 8][cc] = make_float2(acc[mf][nf][2], acc[mf][nf][3]);
        }
    }
}

// ---------------------------------------------------------------------------
// combine (proven)
// ---------------------------------------------------------------------------
__global__ void softmax_combine() {
    int idx = blockIdx.x * blockDim.x + threadIdx.x;
    int b = idx >> 12;
    int p = idx & (HW - 1);
    float m = g_pm[0][b][p];
    float s = g_ps[0][b][p];
    #pragma unroll
    for (int t = 1; t < NTILES; t++) {
        float mt = g_pm[t][b][p];
        float st = g_ps[t][b][p];
        float mn = fmaxf(m, mt);
        s = s * __expf(m - mn) + st * __expf(mt - mn);
        m = mn;
    }
    g_cmax[b][p] = m;
    g_crcp[b][p] = 1.f / s;
}

// ---------------------------------------------------------------------------
// gemm2 (split-K x4): g_part[ls][b][c][p] = sum_{l in split} K[l][c]*softmax(S)[l][p]
// double-buffered BK=16, 64 chunks per split, one sync per chunk
// ---------------------------------------------------------------------------
__global__ __launch_bounds__(256) void gemm2_mma() {
    __shared__ uint32_t sh[2][4][8 * SMS];
    __shared__ float sm[128], sr[128];

    int b = blockIdx.y, p0 = blockIdx.x * 128, ls = blockIdx.z;
    int lbase = ls * (HW / KSPLIT);
    int tid = threadIdx.x, wid = tid >> 5, lane = tid & 31;
    int gid = lane >> 2, tig = lane & 3;
    int wm = (wid & 1) * 64, wn = (wid >> 1) * 32;

    if (tid < 128) {
        sm[tid] = g_cmax[b][p0 + tid];
        sr[tid] = g_crcp[b][p0 + tid];
    }
    __syncthreads();

    const float* Kg = &g_k[b][0][0];   // rows = l, cols = c
    const float* Sg = &g_S[b][0][0];   // rows = l, cols = p

    int pr = tid >> 5, cn = (tid & 31) * 4;

    float4 a0, a1, b0, b1;
    a0 = *(const float4*)(Kg + (size_t)(lbase + 2 * pr)     * C + cn);
    a1 = *(const float4*)(Kg + (size_t)(lbase + 2 * pr + 1) * C + cn);
    b0 = *(const float4*)(Sg + (size_t)(lbase + 2 * pr)     * HW + p0 + cn);
    b1 = *(const float4*)(Sg + (size_t)(lbase + 2 * pr + 1) * HW + p0 + cn);
    {
        uint4 uh, ul;
        bf_split2(a0.x, a1.x, uh.x, ul.x);
        bf_split2(a0.y, a1.y, uh.y, ul.y);
        bf_split2(a0.z, a1.z, uh.z, ul.z);
        bf_split2(a0.w, a1.w, uh.w, ul.w);
        *(uint4*)&sh[0][0][pr*SMS+cn] = uh;
        *(uint4*)&sh[0][1][pr*SMS+cn] = ul;
        float4 e0, e1;
        e0.x = __expf(b0.x - sm[cn+0]) * sr[cn+0]; e1.x = __expf(b1.x - sm[cn+0]) * sr[cn+0];
        e0.y = __expf(b0.y - sm[cn+1]) * sr[cn+1]; e1.y = __expf(b1.y - sm[cn+1]) * sr[cn+1];
        e0.z = __expf(b0.z - sm[cn+2]) * sr[cn+2]; e1.z = __expf(b1.z - sm[cn+2]) * sr[cn+2];
        e0.w = __expf(b0.w - sm[cn+3]) * sr[cn+3]; e1.w = __expf(b1.w - sm[cn+3]) * sr[cn+3];
        bf_split2(e0.x, e1.x, uh.x, ul.x);
        bf_split2(e0.y, e1.y, uh.y, ul.y);
        bf_split2(e0.z, e1.z, uh.z, ul.z);
        bf_split2(e0.w, e1.w, uh.w, ul.w);
        *(uint4*)&sh[0][2][pr*SMS+cn] = uh;
        *(uint4*)&sh[0][3][pr*SMS+cn] = ul;
    }
    __syncthreads();

    float acc[4][4][4] = {};
    const int NIT = (HW / KSPLIT) / 16;   // 64
    for (int it = 0; it < NIT; it++) {
        int st = it & 1;
        if (it < NIT - 1) {
            int l0 = lbase + (it + 1) * 16;
            a0 = *(const float4*)(Kg + (size_t)(l0 + 2 * pr)     * C + cn);
            a1 = *(const float4*)(Kg + (size_t)(l0 + 2 * pr + 1) * C + cn);
            b0 = *(const float4*)(Sg + (size_t)(l0 + 2 * pr)     * HW + p0 + cn);
            b1 = *(const float4*)(Sg + (size_t)(l0 + 2 * pr + 1) * HW + p0 + cn);
        }
        mma_block(sh[st][0], sh[st][1], sh[st][2], sh[st][3], wm, wn, gid, tig, acc);
        if (it < NIT - 1) {
            int ns = st ^ 1;
            uint4 uh, ul;
            bf_split2(a0.x, a1.x, uh.x, ul.x);
            bf_split2(a0.y, a1.y, uh.y, ul.y);
            bf_split2(a0.z, a1.z, uh.z, ul.z);
            bf_split2(a0.w, a1.w, uh.w, ul.w);
            *(uint4*)&sh[ns][0][pr*SMS+cn] = uh;
            *(uint4*)&sh[ns][1][pr*SMS+cn] = ul;
            float4 e0, e1;
            e0.x = __expf(b0.x - sm[cn+0]) * sr[cn+0]; e1.x = __expf(b1.x - sm[cn+0]) * sr[cn+0];
            e0.y = __expf(b0.y - sm[cn+1]) * sr[cn+1]; e1.y = __expf(b1.y - sm[cn+1]) * sr[cn+1];
            e0.z = __expf(b0.z - sm[cn+2]) * sr[cn+2]; e1.z = __expf(b1.z - sm[cn+2]) * sr[cn+2];
            e0.w = __expf(b0.w - sm[cn+3]) * sr[cn+3]; e1.w = __expf(b1.w - sm[cn+3]) * sr[cn+3];
            bf_split2(e0.x, e1.x, uh.x, ul.x);
            bf_split2(e0.y, e1.y, uh.y, ul.y);
            bf_split2(e0.z, e1.z, uh.z, ul.z);
            bf_split2(e0.w, e1.w, uh.w, ul.w);
            *(uint4*)&sh[ns][2][pr*SMS+cn] = uh;
            *(uint4*)&sh[ns][3][pr*SMS+cn] = ul;
            __syncthreads();
        }
    }

    // write partials (same proven index pattern as the S store)
    float* P = &g_part[ls][b][0][0];
    #pragma unroll
    for (int mf = 0; mf < 4; mf++) {
        #pragma unroll
        for (int nf = 0; nf < 4; nf++) {
            int r = wm + mf * 16 + gid;           // c index
            int cc = p0 + wn + nf * 8 + 2 * tig;  // p index
            *(float2*)(P + (size_t)r * HW + cc)       = make_float2(acc[mf][nf][0], acc[mf][nf][1]);
            *(float2*)(P + (size_t)(r + 8) * HW + cc) = make_float2(acc[mf][nf][2], acc[mf][nf][3]);
        }
    }
}

// ---------------------------------------------------------------------------
// combine2: sum split-K partials + mask-blend epilogue
// ---------------------------------------------------------------------------
__global__ void combine2(const float* __restrict__ fg,
                         const float* __restrict__ mask,
                         float* __restrict__ out) {
    int idx = blockIdx.x * blockDim.x + threadIdx.x;   // over NB*C*HW
    int p = idx & (HW - 1);
    int b = idx >> 19;                                 // C*HW = 2^19
    int c = (idx >> 12) & (C - 1);
    float v = 0.f;
    #pragma unroll
    for (int s = 0; s < KSPLIT; s++)
        v += g_part[s][b][c][p];
    float mk = mask[b * HW + p];
    out[idx] = v * (1.f - mk) * (1.f / 9.f) + fg[idx] * mk;
}

extern "C" void kernel_launch(void* const* d_in, const int* in_sizes, int n_in,
                              void* d_out, int out_size) {
    const float* fg   = (const float*)d_in[0];
    const float* mask = (const float*)d_in[1];
    float* out = (float*)d_out;

    k_prep<<<dim3(HW, NB), C>>>(fg);
    y_prep<<<(NB * C * HW) / 256, 256>>>(fg);
    gemm1_mma<<<dim3(HW / 128, HW / 128, NB), 256>>>();
    softmax_combine<<<(NB * HW) / 256, 256>>>();
    gemm2_mma<<<dim3(HW / 128, NB, KSPLIT), 256>>>();
    combine2<<<(NB * C * HW) / 256, 256>>>(fg, mask, out);
}

// round 13
// speedup vs baseline: 1.5583x; 1.5583x over previous
#include <cuda_runtime.h>
#include <cuda_bf16.h>
#include <cstdint>

#define NB 4
#define C 128
#define HW 4096
#define EPSF 1e-7f
#define NTILES (HW / 128)
#define SMS 136      // padded shared stride (uint32 units)
#define KSPLIT 4

// ---------------- scratch ----------------
__device__ __align__(128) float g_k [NB][HW][C];    // K[l][c]
__device__ __align__(128) float g_y [NB][C][HW];    // boxsum [c][p]
__device__ __align__(128) float g_S [NB][HW][HW];   // S[l][p]
__device__ __align__(128) float g_part[KSPLIT][NB][C][HW];  // gemm2 split-K partials
__device__ float g_pm[NTILES][NB][HW];
__device__ float g_ps[NTILES][NB][HW];
__device__ float g_cmax[NB][HW];
__device__ float g_crcp[NB][HW];

// ---------------- helpers (proven) ----------------
__device__ __forceinline__ void bf_split2(float v0, float v1, uint32_t& h, uint32_t& l) {
    __nv_bfloat16 h0 = __float2bfloat16(v0);
    __nv_bfloat16 h1 = __float2bfloat16(v1);
    __nv_bfloat16 l0 = __float2bfloat16(v0 - __bfloat162float(h0));
    __nv_bfloat16 l1 = __float2bfloat16(v1 - __bfloat162float(h1));
    h = (uint32_t)__bfloat16_as_ushort(h0) | ((uint32_t)__bfloat16_as_ushort(h1) << 16);
    l = (uint32_t)__bfloat16_as_ushort(l0) | ((uint32_t)__bfloat16_as_ushort(l1) << 16);
}
__device__ __forceinline__ void mma16(float* c, const uint32_t* a, const uint32_t* b) {
    asm volatile("mma.sync.aligned.m16n8k16.row.col.f32.bf16.bf16.f32 "
        "{%0,%1,%2,%3},{%4,%5,%6,%7},{%8,%9},{%0,%1,%2,%3};"
        : "+f"(c[0]), "+f"(c[1]), "+f"(c[2]), "+f"(c[3])
        : "r"(a[0]), "r"(a[1]), "r"(a[2]), "r"(a[3]), "r"(b[0]), "r"(b[1]));
}

// one BK=16 stage of 3-term split-bf16 mma (proven fragment mapping, kk2=0 only)
__device__ __forceinline__ void mma_block(const uint32_t* pAh, const uint32_t* pAl,
                                          const uint32_t* pBh, const uint32_t* pBl,
                                          int wm, int wn, int gid, int tig,
                                          float acc[4][4][4]) {
    uint32_t ah[4][4], al[4][4], bh[4][2], bl[4][2];
    #pragma unroll
    for (int mf = 0; mf < 4; mf++) {
        int m = wm + mf * 16 + gid;
        ah[mf][0] = pAh[tig * SMS + m];
        ah[mf][1] = pAh[tig * SMS + m + 8];
        ah[mf][2] = pAh[(tig + 4) * SMS + m];
        ah[mf][3] = pAh[(tig + 4) * SMS + m + 8];
        al[mf][0] = pAl[tig * SMS + m];
        al[mf][1] = pAl[tig * SMS + m + 8];
        al[mf][2] = pAl[(tig + 4) * SMS + m];
        al[mf][3] = pAl[(tig + 4) * SMS + m + 8];
    }
    #pragma unroll
    for (int nf = 0; nf < 4; nf++) {
        int n = wn + nf * 8 + gid;
        bh[nf][0] = pBh[tig * SMS + n];
        bh[nf][1] = pBh[(tig + 4) * SMS + n];
        bl[nf][0] = pBl[tig * SMS + n];
        bl[nf][1] = pBl[(tig + 4) * SMS + n];
    }
    #pragma unroll
    for (int mf = 0; mf < 4; mf++)
        #pragma unroll
        for (int nf = 0; nf < 4; nf++) {
            mma16(acc[mf][nf], ah[mf], bl[nf]);
            mma16(acc[mf][nf], al[mf], bh[nf]);
            mma16(acc[mf][nf], ah[mf], bh[nf]);
        }
}

// ---------------------------------------------------------------------------
// prep (proven)
// ---------------------------------------------------------------------------
__global__ void k_prep(const float* __restrict__ fg) {
    int l = blockIdx.x, b = blockIdx.y, c = threadIdx.x;
    float v = fg[((b * C + c) * HW) + l] + EPSF;
    float s = v * v;
    #pragma unroll
    for (int o = 16; o > 0; o >>= 1) s += __shfl_xor_sync(0xffffffffu, s, o);
    __shared__ float ws[4];
    if ((c & 31) == 0) ws[c >> 5] = s;
    __syncthreads();
    float tot = ws[0] + ws[1] + ws[2] + ws[3];
    g_k[b][l][c] = v * rsqrtf(tot);
}

__global__ void y_prep(const float* __restrict__ fg) {
    int idx = blockIdx.x * blockDim.x + threadIdx.x;
    int p = idx & (HW - 1);
    int bc = idx >> 12;
    int i = p >> 6, j = p & 63;
    const float* base = fg + (size_t)bc * HW;
    float s = 0.f;
    #pragma unroll
    for (int di = -1; di <= 1; di++) {
        int ii = i + di;
        if (ii < 0 || ii >= 64) continue;
        #pragma unroll
        for (int dj = -1; dj <= 1; dj++) {
            int jj = j + dj;
            if (jj < 0 || jj >= 64) continue;
            s += base[ii * 64 + jj];
        }
    }
    ((float*)g_y)[idx] = s;
}

// ---------------------------------------------------------------------------
// gemm1: S[l][p] = K[l][:] . Y[:,p]  + partial stats
// double-buffered BK=16, 8 chunks, one sync per chunk
// ---------------------------------------------------------------------------
__global__ __launch_bounds__(256) void gemm1_mma() {
    __shared__ uint32_t sh[2][4][8 * SMS];   // [stage][Ah,Al,Bh,Bl][k2*SMS+col]
    __shared__ float pm_sh[2][128], ps_sh[2][128];

    int b = blockIdx.z, lt = blockIdx.y;
    int l0 = lt * 128, p0 = blockIdx.x * 128;
    int tid = threadIdx.x, wid = tid >> 5, lane = tid & 31;
    int gid = lane >> 2, tig = lane & 3;
    int wm = (wid & 1) * 64, wn = (wid >> 1) * 32;

    const float* Ag = &g_k[b][l0][0];   // rows = m (l), cols = k (c)
    const float* Bg = &g_y[b][0][p0];   // rows = k (c), cols = n (p)

    int am = tid & 127, ah4 = (tid >> 7) * 4;   // A: row am, pairs [ah4, ah4+4)
    int pr = tid >> 5,  bn = (tid & 31) * 4;    // B: pair-row pr, n [bn, bn+4)

    float4 a0, a1, b0, b1;
    a0 = *(const float4*)(Ag + am * C + ah4 * 2);
    a1 = *(const float4*)(Ag + am * C + ah4 * 2 + 4);
    b0 = *(const float4*)(Bg + (size_t)(2 * pr) * HW + bn);
    b1 = *(const float4*)(Bg + (size_t)(2 * pr + 1) * HW + bn);
    {
        uint32_t h, l;
        bf_split2(a0.x, a0.y, h, l); sh[0][0][(ah4+0)*SMS+am] = h; sh[0][1][(ah4+0)*SMS+am] = l;
        bf_split2(a0.z, a0.w, h, l); sh[0][0][(ah4+1)*SMS+am] = h; sh[0][1][(ah4+1)*SMS+am] = l;
        bf_split2(a1.x, a1.y, h, l); sh[0][0][(ah4+2)*SMS+am] = h; sh[0][1][(ah4+2)*SMS+am] = l;
        bf_split2(a1.z, a1.w, h, l); sh[0][0][(ah4+3)*SMS+am] = h; sh[0][1][(ah4+3)*SMS+am] = l;
        uint4 uh, ul;
        bf_split2(b0.x, b1.x, uh.x, ul.x);
        bf_split2(b0.y, b1.y, uh.y, ul.y);
        bf_split2(b0.z, b1.z, uh.z, ul.z);
        bf_split2(b0.w, b1.w, uh.w, ul.w);
        *(uint4*)&sh[0][2][pr*SMS+bn] = uh;
        *(uint4*)&sh[0][3][pr*SMS+bn] = ul;
    }
    __syncthreads();

    float acc[4][4][4] = {};
    for (int it = 0; it < 8; it++) {
        int st = it & 1;
        if (it < 7) {
            int c0 = (it + 1) * 16;
            a0 = *(const float4*)(Ag + am * C + c0 + ah4 * 2);
            a1 = *(const float4*)(Ag + am * C + c0 + ah4 * 2 + 4);
            b0 = *(const float4*)(Bg + (size_t)(c0 + 2 * pr) * HW + bn);
            b1 = *(const float4*)(Bg + (size_t)(c0 + 2 * pr + 1) * HW + bn);
        }
        mma_block(sh[st][0], sh[st][1], sh[st][2], sh[st][3], wm, wn, gid, tig, acc);
        if (it < 7) {
            int ns = st ^ 1;
            uint32_t h, l;
            bf_split2(a0.x, a0.y, h, l); sh[ns][0][(ah4+0)*SMS+am] = h; sh[ns][1][(ah4+0)*SMS+am] = l;
            bf_split2(a0.z, a0.w, h, l); sh[ns][0][(ah4+1)*SMS+am] = h; sh[ns][1][(ah4+1)*SMS+am] = l;
            bf_split2(a1.x, a1.y, h, l); sh[ns][0][(ah4+2)*SMS+am] = h; sh[ns][1][(ah4+2)*SMS+am] = l;
            bf_split2(a1.z, a1.w, h, l); sh[ns][0][(ah4+3)*SMS+am] = h; sh[ns][1][(ah4+3)*SMS+am] = l;
            uint4 uh, ul;
            bf_split2(b0.x, b1.x, uh.x, ul.x);
            bf_split2(b0.y, b1.y, uh.y, ul.y);
            bf_split2(b0.z, b1.z, uh.z, ul.z);
            bf_split2(b0.w, b1.w, uh.w, ul.w);
            *(uint4*)&sh[ns][2][pr*SMS+bn] = uh;
            *(uint4*)&sh[ns][3][pr*SMS+bn] = ul;
            __syncthreads();
        }
    }

    // ---- partial softmax stats (proven) ----
    #pragma unroll
    for (int nf = 0; nf < 4; nf++) {
        #pragma unroll
        for (int h = 0; h < 2; h++) {
            float mx = -1e30f;
            #pragma unroll
            for (int mf = 0; mf < 4; mf++)
                mx = fmaxf(mx, fmaxf(acc[mf][nf][h], acc[mf][nf][2 + h]));
            float sum = 0.f;
            #pragma unroll
            for (int mf = 0; mf < 4; mf++)
                sum += __expf(acc[mf][nf][h] - mx) + __expf(acc[mf][nf][2 + h] - mx);
            #pragma unroll
            for (int off = 4; off < 32; off <<= 1) {
                float mo = __shfl_xor_sync(0xffffffffu, mx, off);
                float so = __shfl_xor_sync(0xffffffffu, sum, off);
                float mn = fmaxf(mx, mo);
                sum = sum * __expf(mx - mn) + so * __expf(mo - mn);
                mx = mn;
            }
            if (gid == 0) {
                int col = wn + nf * 8 + 2 * tig + h;
                pm_sh[wid & 1][col] = mx;
                ps_sh[wid & 1][col] = sum;
            }
        }
    }
    __syncthreads();
    if (tid < 128) {
        float m0 = pm_sh[0][tid], m1 = pm_sh[1][tid];
        float mn = fmaxf(m0, m1);
        float s = ps_sh[0][tid] * __expf(m0 - mn) + ps_sh[1][tid] * __expf(m1 - mn);
        g_pm[lt][b][p0 + tid] = mn;
        g_ps[lt][b][p0 + tid] = s;
    }

    // ---- store S tile (proven) ----
    #pragma unroll
    for (int mf = 0; mf < 4; mf++) {
        #pragma unroll
        for (int nf = 0; nf < 4; nf++) {
            int r = l0 + wm + mf * 16 + gid;
            int cc = p0 + wn + nf * 8 + 2 * tig;
            *(float2*)&g_S[b][r][cc]     = make_float2(acc[mf][nf][0], acc[mf][nf][1]);
            *(float2*)&g_S[b][r + 8][cc] = make_float2(acc[mf][nf][2], acc[mf][nf][3]);
        }
    }
}

// ---------------------------------------------------------------------------
// combine (proven)
// ---------------------------------------------------------------------------
__global__ void softmax_combine() {
    int idx = blockIdx.x * blockDim.x + threadIdx.x;
    int b = idx >> 12;
    int p = idx & (HW - 1);
    float m = g_pm[0][b][p];
    float s = g_ps[0][b][p];
    #pragma unroll
    for (int t = 1; t < NTILES; t++) {
        float mt = g_pm[t][b][p];
        float st = g_ps[t][b][p];
        float mn = fmaxf(m, mt);
        s = s * __expf(m - mn) + st * __expf(mt - mn);
        m = mn;
    }
    g_cmax[b][p] = m;
    g_crcp[b][p] = 1.f / s;
}

// ---------------------------------------------------------------------------
// gemm2 (split-K x4): g_part[ls][b][c][p] = sum_{l in split} K[l][c]*softmax(S)[l][p]
// double-buffered BK=16, 64 chunks per split, one sync per chunk
// ---------------------------------------------------------------------------
__global__ __launch_bounds__(256) void gemm2_mma() {
    __shared__ uint32_t sh[2][4][8 * SMS];
    __shared__ float sm[128], sr[128];

    int b = blockIdx.y, p0 = blockIdx.x * 128, ls = blockIdx.z;
    int lbase = ls * (HW / KSPLIT);
    int tid = threadIdx.x, wid = tid >> 5, lane = tid & 31;
    int gid = lane >> 2, tig = lane & 3;
    int wm = (wid & 1) * 64, wn = (wid >> 1) * 32;

    if (tid < 128) {
        sm[tid] = g_cmax[b][p0 + tid];
        sr[tid] = g_crcp[b][p0 + tid];
    }
    __syncthreads();

    const float* Kg = &g_k[b][0][0];   // rows = l, cols = c
    const float* Sg = &g_S[b][0][0];   // rows = l, cols = p

    int pr = tid >> 5, cn = (tid & 31) * 4;

    float4 a0, a1, b0, b1;
    a0 = *(const float4*)(Kg + (size_t)(lbase + 2 * pr)     * C + cn);
    a1 = *(const float4*)(Kg + (size_t)(lbase + 2 * pr + 1) * C + cn);
    b0 = *(const float4*)(Sg + (size_t)(lbase + 2 * pr)     * HW + p0 + cn);
    b1 = *(const float4*)(Sg + (size_t)(lbase + 2 * pr + 1) * HW + p0 + cn);
    {
        uint4 uh, ul;
        bf_split2(a0.x, a1.x, uh.x, ul.x);
        bf_split2(a0.y, a1.y, uh.y, ul.y);
        bf_split2(a0.z, a1.z, uh.z, ul.z);
        bf_split2(a0.w, a1.w, uh.w, ul.w);
        *(uint4*)&sh[0][0][pr*SMS+cn] = uh;
        *(uint4*)&sh[0][1][pr*SMS+cn] = ul;
        float4 e0, e1;
        e0.x = __expf(b0.x - sm[cn+0]) * sr[cn+0]; e1.x = __expf(b1.x - sm[cn+0]) * sr[cn+0];
        e0.y = __expf(b0.y - sm[cn+1]) * sr[cn+1]; e1.y = __expf(b1.y - sm[cn+1]) * sr[cn+1];
        e0.z = __expf(b0.z - sm[cn+2]) * sr[cn+2]; e1.z = __expf(b1.z - sm[cn+2]) * sr[cn+2];
        e0.w = __expf(b0.w - sm[cn+3]) * sr[cn+3]; e1.w = __expf(b1.w - sm[cn+3]) * sr[cn+3];
        bf_split2(e0.x, e1.x, uh.x, ul.x);
        bf_split2(e0.y, e1.y, uh.y, ul.y);
        bf_split2(e0.z, e1.z, uh.z, ul.z);
        bf_split2(e0.w, e1.w, uh.w, ul.w);
        *(uint4*)&sh[0][2][pr*SMS+cn] = uh;
        *(uint4*)&sh[0][3][pr*SMS+cn] = ul;
    }
    __syncthreads();

    float acc[4][4][4] = {};
    const int NIT = (HW / KSPLIT) / 16;   // 64
    for (int it = 0; it < NIT; it++) {
        int st = it & 1;
        if (it < NIT - 1) {
            int l0 = lbase + (it + 1) * 16;
            a0 = *(const float4*)(Kg + (size_t)(l0 + 2 * pr)     * C + cn);
            a1 = *(const float4*)(Kg + (size_t)(l0 + 2 * pr + 1) * C + cn);
            b0 = *(const float4*)(Sg + (size_t)(l0 + 2 * pr)     * HW + p0 + cn);
            b1 = *(const float4*)(Sg + (size_t)(l0 + 2 * pr + 1) * HW + p0 + cn);
        }
        mma_block(sh[st][0], sh[st][1], sh[st][2], sh[st][3], wm, wn, gid, tig, acc);
        if (it < NIT - 1) {
            int ns = st ^ 1;
            uint4 uh, ul;
            bf_split2(a0.x, a1.x, uh.x, ul.x);
            bf_split2(a0.y, a1.y, uh.y, ul.y);
            bf_split2(a0.z, a1.z, uh.z, ul.z);
            bf_split2(a0.w, a1.w, uh.w, ul.w);
            *(uint4*)&sh[ns][0][pr*SMS+cn] = uh;
            *(uint4*)&sh[ns][1][pr*SMS+cn] = ul;
            float4 e0, e1;
            e0.x = __expf(b0.x - sm[cn+0]) * sr[cn+0]; e1.x = __expf(b1.x - sm[cn+0]) * sr[cn+0];
            e0.y = __expf(b0.y - sm[cn+1]) * sr[cn+1]; e1.y = __expf(b1.y - sm[cn+1]) * sr[cn+1];
            e0.z = __expf(b0.z - sm[cn+2]) * sr[cn+2]; e1.z = __expf(b1.z - sm[cn+2]) * sr[cn+2];
            e0.w = __expf(b0.w - sm[cn+3]) * sr[cn+3]; e1.w = __expf(b1.w - sm[cn+3]) * sr[cn+3];
            bf_split2(e0.x, e1.x, uh.x, ul.x);
            bf_split2(e0.y, e1.y, uh.y, ul.y);
            bf_split2(e0.z, e1.z, uh.z, ul.z);
            bf_split2(e0.w, e1.w, uh.w, ul.w);
            *(uint4*)&sh[ns][2][pr*SMS+cn] = uh;
            *(uint4*)&sh[ns][3][pr*SMS+cn] = ul;
            __syncthreads();
        }
    }

    // write partials (same proven index pattern as the S store)
    float* P = &g_part[ls][b][0][0];
    #pragma unroll
    for (int mf = 0; mf < 4; mf++) {
        #pragma unroll
        for (int nf = 0; nf < 4; nf++) {
            int r = wm + mf * 16 + gid;           // c index
            int cc = p0 + wn + nf * 8 + 2 * tig;  // p index
            *(float2*)(P + (size_t)r * HW + cc)       = make_float2(acc[mf][nf][0], acc[mf][nf][1]);
            *(float2*)(P + (size_t)(r + 8) * HW + cc) = make_float2(acc[mf][nf][2], acc[mf][nf][3]);
        }
    }
}

// ---------------------------------------------------------------------------
// combine2: sum split-K partials + mask-blend epilogue
// ---------------------------------------------------------------------------
__global__ void combine2(const float* __restrict__ fg,
                         const float* __restrict__ mask,
                         float* __restrict__ out) {
    int idx = blockIdx.x * blockDim.x + threadIdx.x;   // over NB*C*HW
    int p = idx & (HW - 1);
    int b = idx >> 19;                                 // C*HW = 2^19
    int c = (idx >> 12) & (C - 1);
    float v = 0.f;
    #pragma unroll
    for (int s = 0; s < KSPLIT; s++)
        v += g_part[s][b][c][p];
    float mk = mask[b * HW + p];
    out[idx] = v * (1.f - mk) * (1.f / 9.f) + fg[idx] * mk;
}

extern "C" void kernel_launch(void* const* d_in, const int* in_sizes, int n_in,
                              void* d_out, int out_size) {
    const float* fg   = (const float*)d_in[0];
    const float* mask = (const float*)d_in[1];
    float* out = (float*)d_out;

    k_prep<<<dim3(HW, NB), C>>>(fg);
    y_prep<<<(NB * C * HW) / 256, 256>>>(fg);
    gemm1_mma<<<dim3(HW / 128, HW / 128, NB), 256>>>();
    softmax_combine<<<(NB * HW) / 256, 256>>>();
    gemm2_mma<<<dim3(HW / 128, NB, KSPLIT), 256>>>();
    combine2<<<(NB * C * HW) / 256, 256>>>(fg, mask, out);
}

// round 14
// speedup vs baseline: 2.1244x; 1.3633x over previous
#include <cuda_runtime.h>
#include <cuda_bf16.h>
#include <cstdint>

#define NB 4
#define C 128
#define HW 4096
#define EPSF 1e-7f
#define NTILES (HW / 128)
#define SMS 136      // padded shared stride (uint32 units)
#define KSPLIT 4

// ---------------- scratch ----------------
__device__ __align__(128) float g_k [NB][HW][C];    // K[l][c]
__device__ __align__(128) float g_y [NB][C][HW];    // boxsum [c][p]
__device__ __align__(128) float g_S [NB][HW][HW];   // S[l][p]
__device__ __align__(128) float g_part[KSPLIT][NB][C][HW];  // gemm2 split-K partials
__device__ float g_pm[NTILES][NB][HW];
__device__ float g_ps[NTILES][NB][HW];
__device__ float g_cmax[NB][HW];
__device__ float g_crcp[NB][HW];

// ---------------- helpers ----------------
__device__ __forceinline__ uint32_t bf_pack2(float v0, float v1) {
    return (uint32_t)__bfloat16_as_ushort(__float2bfloat16(v0)) |
           ((uint32_t)__bfloat16_as_ushort(__float2bfloat16(v1)) << 16);
}
__device__ __forceinline__ void mma16(float* c, const uint32_t* a, const uint32_t* b) {
    asm volatile("mma.sync.aligned.m16n8k16.row.col.f32.bf16.bf16.f32 "
        "{%0,%1,%2,%3},{%4,%5,%6,%7},{%8,%9},{%0,%1,%2,%3};"
        : "+f"(c[0]), "+f"(c[1]), "+f"(c[2]), "+f"(c[3])
        : "r"(a[0]), "r"(a[1]), "r"(a[2]), "r"(a[3]), "r"(b[0]), "r"(b[1]));
}

// one BK=16 stage of single-pass bf16 mma (proven fragment mapping)
__device__ __forceinline__ void mma_block(const uint32_t* pA, const uint32_t* pB,
                                          int wm, int wn, int gid, int tig,
                                          float acc[4][4][4]) {
    uint32_t a[4][4], bb[4][2];
    #pragma unroll
    for (int mf = 0; mf < 4; mf++) {
        int m = wm + mf * 16 + gid;
        a[mf][0] = pA[tig * SMS + m];
        a[mf][1] = pA[tig * SMS + m + 8];
        a[mf][2] = pA[(tig + 4) * SMS + m];
        a[mf][3] = pA[(tig + 4) * SMS + m + 8];
    }
    #pragma unroll
    for (int nf = 0; nf < 4; nf++) {
        int n = wn + nf * 8 + gid;
        bb[nf][0] = pB[tig * SMS + n];
        bb[nf][1] = pB[(tig + 4) * SMS + n];
    }
    #pragma unroll
    for (int mf = 0; mf < 4; mf++)
        #pragma unroll
        for (int nf = 0; nf < 4; nf++)
            mma16(acc[mf][nf], a[mf], bb[nf]);
}

// ---------------------------------------------------------------------------
// k_prep (coalesced rewrite): tile 32 l-columns, transpose in smem,
// compute per-l norm, write g_k[l][c] rows coalesced.
// grid (HW/32, NB), block (32, 8)
// ---------------------------------------------------------------------------
__global__ void k_prep(const float* __restrict__ fg) {
    __shared__ float t[128][33];
    __shared__ float ps[8][32];
    __shared__ float rn[32];
    int l0 = blockIdx.x * 32, b = blockIdx.y;
    int tx = threadIdx.x, ty = threadIdx.y;

    #pragma unroll
    for (int cc = ty; cc < C; cc += 8)
        t[cc][tx] = fg[((size_t)(b * C + cc)) * HW + l0 + tx] + EPSF;
    __syncthreads();

    float s = 0.f;
    #pragma unroll
    for (int cc = ty * 16; cc < ty * 16 + 16; cc++) {
        float v = t[cc][tx];
        s += v * v;
    }
    ps[ty][tx] = s;
    __syncthreads();
    if (ty == 0) {
        float tot = 0.f;
        #pragma unroll
        for (int j = 0; j < 8; j++) tot += ps[j][tx];
        rn[tx] = rsqrtf(tot);
    }
    __syncthreads();

    #pragma unroll
    for (int li = ty; li < 32; li += 8) {
        float r = rn[li];
        #pragma unroll
        for (int cc = tx; cc < C; cc += 32)
            g_k[b][l0 + li][cc] = t[cc][li] * r;
    }
}

// ---------------------------------------------------------------------------
// y_prep (proven)
// ---------------------------------------------------------------------------
__global__ void y_prep(const float* __restrict__ fg) {
    int idx = blockIdx.x * blockDim.x + threadIdx.x;
    int p = idx & (HW - 1);
    int bc = idx >> 12;
    int i = p >> 6, j = p & 63;
    const float* base = fg + (size_t)bc * HW;
    float s = 0.f;
    #pragma unroll
    for (int di = -1; di <= 1; di++) {
        int ii = i + di;
        if (ii < 0 || ii >= 64) continue;
        #pragma unroll
        for (int dj = -1; dj <= 1; dj++) {
            int jj = j + dj;
            if (jj < 0 || jj >= 64) continue;
            s += base[ii * 64 + jj];
        }
    }
    ((float*)g_y)[idx] = s;
}

// ---------------------------------------------------------------------------
// gemm1 (bf16): S[l][p] = K[l][:] . Y[:,p]  + partial stats
// double-buffered BK=16, 8 chunks
// ---------------------------------------------------------------------------
__global__ __launch_bounds__(256) void gemm1_mma() {
    __shared__ uint32_t sh[2][2][8 * SMS];   // [stage][A,B][k2*SMS+col]
    __shared__ float pm_sh[2][128], ps_sh[2][128];

    int b = blockIdx.z, lt = blockIdx.y;
    int l0 = lt * 128, p0 = blockIdx.x * 128;
    int tid = threadIdx.x, wid = tid >> 5, lane = tid & 31;
    int gid = lane >> 2, tig = lane & 3;
    int wm = (wid & 1) * 64, wn = (wid >> 1) * 32;

    const float* Ag = &g_k[b][l0][0];   // rows = m (l), cols = k (c)
    const float* Bg = &g_y[b][0][p0];   // rows = k (c), cols = n (p)

    int am = tid & 127, ah4 = (tid >> 7) * 4;   // A: row am, pairs [ah4, ah4+4)
    int pr = tid >> 5,  bn = (tid & 31) * 4;    // B: pair-row pr, n [bn, bn+4)

    float4 a0, a1, b0, b1;
    a0 = *(const float4*)(Ag + am * C + ah4 * 2);
    a1 = *(const float4*)(Ag + am * C + ah4 * 2 + 4);
    b0 = *(const float4*)(Bg + (size_t)(2 * pr) * HW + bn);
    b1 = *(const float4*)(Bg + (size_t)(2 * pr + 1) * HW + bn);
    {
        sh[0][0][(ah4+0)*SMS+am] = bf_pack2(a0.x, a0.y);
        sh[0][0][(ah4+1)*SMS+am] = bf_pack2(a0.z, a0.w);
        sh[0][0][(ah4+2)*SMS+am] = bf_pack2(a1.x, a1.y);
        sh[0][0][(ah4+3)*SMS+am] = bf_pack2(a1.z, a1.w);
        uint4 u;
        u.x = bf_pack2(b0.x, b1.x);
        u.y = bf_pack2(b0.y, b1.y);
        u.z = bf_pack2(b0.z, b1.z);
        u.w = bf_pack2(b0.w, b1.w);
        *(uint4*)&sh[0][1][pr*SMS+bn] = u;
    }
    __syncthreads();

    float acc[4][4][4] = {};
    for (int it = 0; it < 8; it++) {
        int st = it & 1;
        if (it < 7) {
            int c0 = (it + 1) * 16;
            a0 = *(const float4*)(Ag + am * C + c0 + ah4 * 2);
            a1 = *(const float4*)(Ag + am * C + c0 + ah4 * 2 + 4);
            b0 = *(const float4*)(Bg + (size_t)(c0 + 2 * pr) * HW + bn);
            b1 = *(const float4*)(Bg + (size_t)(c0 + 2 * pr + 1) * HW + bn);
        }
        mma_block(sh[st][0], sh[st][1], wm, wn, gid, tig, acc);
        if (it < 7) {
            int ns = st ^ 1;
            sh[ns][0][(ah4+0)*SMS+am] = bf_pack2(a0.x, a0.y);
            sh[ns][0][(ah4+1)*SMS+am] = bf_pack2(a0.z, a0.w);
            sh[ns][0][(ah4+2)*SMS+am] = bf_pack2(a1.x, a1.y);
            sh[ns][0][(ah4+3)*SMS+am] = bf_pack2(a1.z, a1.w);
            uint4 u;
            u.x = bf_pack2(b0.x, b1.x);
            u.y = bf_pack2(b0.y, b1.y);
            u.z = bf_pack2(b0.z, b1.z);
            u.w = bf_pack2(b0.w, b1.w);
            *(uint4*)&sh[ns][1][pr*SMS+bn] = u;
            __syncthreads();
        }
    }

    // ---- partial softmax stats (proven) ----
    #pragma unroll
    for (int nf = 0; nf < 4; nf++) {
        #pragma unroll
        for (int h = 0; h < 2; h++) {
            float mx = -1e30f;
            #pragma unroll
            for (int mf = 0; mf < 4; mf++)
                mx = fmaxf(mx, fmaxf(acc[mf][nf][h], acc[mf][nf][2 + h]));
            float sum = 0.f;
            #pragma unroll
            for (int mf = 0; mf < 4; mf++)
                sum += __expf(acc[mf][nf][h] - mx) + __expf(acc[mf][nf][2 + h] - mx);
            #pragma unroll
            for (int off = 4; off < 32; off <<= 1) {
                float mo = __shfl_xor_sync(0xffffffffu, mx, off);
                float so = __shfl_xor_sync(0xffffffffu, sum, off);
                float mn = fmaxf(mx, mo);
                sum = sum * __expf(mx - mn) + so * __expf(mo - mn);
                mx = mn;
            }
            if (gid == 0) {
                int col = wn + nf * 8 + 2 * tig + h;
                pm_sh[wid & 1][col] = mx;
                ps_sh[wid & 1][col] = sum;
            }
        }
    }
    __syncthreads();
    if (tid < 128) {
        float m0 = pm_sh[0][tid], m1 = pm_sh[1][tid];
        float mn = fmaxf(m0, m1);
        float s = ps_sh[0][tid] * __expf(m0 - mn) + ps_sh[1][tid] * __expf(m1 - mn);
        g_pm[lt][b][p0 + tid] = mn;
        g_ps[lt][b][p0 + tid] = s;
    }

    // ---- store S tile (proven) ----
    #pragma unroll
    for (int mf = 0; mf < 4; mf++) {
        #pragma unroll
        for (int nf = 0; nf < 4; nf++) {
            int r = l0 + wm + mf * 16 + gid;
            int cc = p0 + wn + nf * 8 + 2 * tig;
            *(float2*)&g_S[b][r][cc]     = make_float2(acc[mf][nf][0], acc[mf][nf][1]);
            *(float2*)&g_S[b][r + 8][cc] = make_float2(acc[mf][nf][2], acc[mf][nf][3]);
        }
    }
}

// ---------------------------------------------------------------------------
// combine (proven)
// ---------------------------------------------------------------------------
__global__ void softmax_combine() {
    int idx = blockIdx.x * blockDim.x + threadIdx.x;
    int b = idx >> 12;
    int p = idx & (HW - 1);
    float m = g_pm[0][b][p];
    float s = g_ps[0][b][p];
    #pragma unroll
    for (int t = 1; t < NTILES; t++) {
        float mt = g_pm[t][b][p];
        float st = g_ps[t][b][p];
        float mn = fmaxf(m, mt);
        s = s * __expf(m - mn) + st * __expf(mt - mn);
        m = mn;
    }
    g_cmax[b][p] = m;
    g_crcp[b][p] = 1.f / s;
}

// ---------------------------------------------------------------------------
// gemm2 (bf16, split-K x4): g_part[ls][b][c][p] = sum_{l in split} K[l][c]*w[l][p]
// double-buffered BK=16, 64 chunks per split
// ---------------------------------------------------------------------------
__global__ __launch_bounds__(256) void gemm2_mma() {
    __shared__ uint32_t sh[2][2][8 * SMS];
    __shared__ float sm[128], sr[128];

    int b = blockIdx.y, p0 = blockIdx.x * 128, ls = blockIdx.z;
    int lbase = ls * (HW / KSPLIT);
    int tid = threadIdx.x, wid = tid >> 5, lane = tid & 31;
    int gid = lane >> 2, tig = lane & 3;
    int wm = (wid & 1) * 64, wn = (wid >> 1) * 32;

    if (tid < 128) {
        sm[tid] = g_cmax[b][p0 + tid];
        sr[tid] = g_crcp[b][p0 + tid];
    }
    __syncthreads();

    const float* Kg = &g_k[b][0][0];   // rows = l, cols = c
    const float* Sg = &g_S[b][0][0];   // rows = l, cols = p

    int pr = tid >> 5, cn = (tid & 31) * 4;

    float4 a0, a1, b0, b1;
    a0 = *(const float4*)(Kg + (size_t)(lbase + 2 * pr)     * C + cn);
    a1 = *(const float4*)(Kg + (size_t)(lbase + 2 * pr + 1) * C + cn);
    b0 = *(const float4*)(Sg + (size_t)(lbase + 2 * pr)     * HW + p0 + cn);
    b1 = *(const float4*)(Sg + (size_t)(lbase + 2 * pr + 1) * HW + p0 + cn);
    {
        uint4 u;
        u.x = bf_pack2(a0.x, a1.x);
        u.y = bf_pack2(a0.y, a1.y);
        u.z = bf_pack2(a0.z, a1.z);
        u.w = bf_pack2(a0.w, a1.w);
        *(uint4*)&sh[0][0][pr*SMS+cn] = u;
        u.x = bf_pack2(__expf(b0.x - sm[cn+0]) * sr[cn+0], __expf(b1.x - sm[cn+0]) * sr[cn+0]);
        u.y = bf_pack2(__expf(b0.y - sm[cn+1]) * sr[cn+1], __expf(b1.y - sm[cn+1]) * sr[cn+1]);
        u.z = bf_pack2(__expf(b0.z - sm[cn+2]) * sr[cn+2], __expf(b1.z - sm[cn+2]) * sr[cn+2]);
        u.w = bf_pack2(__expf(b0.w - sm[cn+3]) * sr[cn+3], __expf(b1.w - sm[cn+3]) * sr[cn+3]);
        *(uint4*)&sh[0][1][pr*SMS+cn] = u;
    }
    __syncthreads();

    float acc[4][4][4] = {};
    const int NIT = (HW / KSPLIT) / 16;   // 64
    for (int it = 0; it < NIT; it++) {
        int st = it & 1;
        if (it < NIT - 1) {
            int l0 = lbase + (it + 1) * 16;
            a0 = *(const float4*)(Kg + (size_t)(l0 + 2 * pr)     * C + cn);
            a1 = *(const float4*)(Kg + (size_t)(l0 + 2 * pr + 1) * C + cn);
            b0 = *(const float4*)(Sg + (size_t)(l0 + 2 * pr)     * HW + p0 + cn);
            b1 = *(const float4*)(Sg + (size_t)(l0 + 2 * pr + 1) * HW + p0 + cn);
        }
        mma_block(sh[st][0], sh[st][1], wm, wn, gid, tig, acc);
        if (it < NIT - 1) {
            int ns = st ^ 1;
            uint4 u;
            u.x = bf_pack2(a0.x, a1.x);
            u.y = bf_pack2(a0.y, a1.y);
            u.z = bf_pack2(a0.z, a1.z);
            u.w = bf_pack2(a0.w, a1.w);
            *(uint4*)&sh[ns][0][pr*SMS+cn] = u;
            u.x = bf_pack2(__expf(b0.x - sm[cn+0]) * sr[cn+0], __expf(b1.x - sm[cn+0]) * sr[cn+0]);
            u.y = bf_pack2(__expf(b0.y - sm[cn+1]) * sr[cn+1], __expf(b1.y - sm[cn+1]) * sr[cn+1]);
            u.z = bf_pack2(__expf(b0.z - sm[cn+2]) * sr[cn+2], __expf(b1.z - sm[cn+2]) * sr[cn+2]);
            u.w = bf_pack2(__expf(b0.w - sm[cn+3]) * sr[cn+3], __expf(b1.w - sm[cn+3]) * sr[cn+3]);
            *(uint4*)&sh[ns][1][pr*SMS+cn] = u;
            __syncthreads();
        }
    }

    // write partials (proven index pattern)
    float* P = &g_part[ls][b][0][0];
    #pragma unroll
    for (int mf = 0; mf < 4; mf++) {
        #pragma unroll
        for (int nf = 0; nf < 4; nf++) {
            int r = wm + mf * 16 + gid;           // c index
            int cc = p0 + wn + nf * 8 + 2 * tig;  // p index
            *(float2*)(P + (size_t)r * HW + cc)       = make_float2(acc[mf][nf][0], acc[mf][nf][1]);
            *(float2*)(P + (size_t)(r + 8) * HW + cc) = make_float2(acc[mf][nf][2], acc[mf][nf][3]);
        }
    }
}

// ---------------------------------------------------------------------------
// combine2: sum split-K partials + mask-blend epilogue (proven)
// ---------------------------------------------------------------------------
__global__ void combine2(const float* __restrict__ fg,
                         const float* __restrict__ mask,
                         float* __restrict__ out) {
    int idx = blockIdx.x * blockDim.x + threadIdx.x;   // over NB*C*HW
    int p = idx & (HW - 1);
    int b = idx >> 19;                                 // C*HW = 2^19
    int c = (idx >> 12) & (C - 1);
    float v = 0.f;
    #pragma unroll
    for (int s = 0; s < KSPLIT; s++)
        v += g_part[s][b][c][p];
    float mk = mask[b * HW + p];
    out[idx] = v * (1.f - mk) * (1.f / 9.f) + fg[idx] * mk;
}

extern "C" void kernel_launch(void* const* d_in, const int* in_sizes, int n_in,
                              void* d_out, int out_size) {
    const float* fg   = (const float*)d_in[0];
    const float* mask = (const float*)d_in[1];
    float* out = (float*)d_out;

    k_prep<<<dim3(HW / 32, NB), dim3(32, 8)>>>(fg);
    y_prep<<<(NB * C * HW) / 256, 256>>>(fg);
    gemm1_mma<<<dim3(HW / 128, HW / 128, NB), 256>>>();
    softmax_combine<<<(NB * HW) / 256, 256>>>();
    gemm2_mma<<<dim3(HW / 128, NB, KSPLIT), 256>>>();
    combine2<<<(NB * C * HW) / 256, 256>>>(fg, mask, out);
}

// round 15
// speedup vs baseline: 2.4779x; 1.1664x over previous
#include <cuda_runtime.h>
#include <cuda_bf16.h>
#include <cstdint>

#define NB 4
#define C 128
#define HW 4096
#define EPSF 1e-7f
#define NTILES (HW / 128)
#define SMS 136      // padded shared stride (uint32 units)
#define KSPLIT 4

// ---------------- scratch ----------------
__device__ __align__(128) __nv_bfloat16 g_k[NB][HW][C];    // K[l][c] bf16
__device__ __align__(128) __nv_bfloat16 g_y[NB][C][HW];    // boxsum [c][p] bf16
__device__ __align__(128) __nv_bfloat16 g_E[NB][HW][HW];   // exp(S - tilemax) bf16
__device__ __align__(128) float g_part[KSPLIT][NB][C][HW]; // gemm2 split-K partials
__device__ float g_pm[NTILES][NB][HW];
__device__ float g_ps[NTILES][NB][HW];
__device__ float g_cmax[NB][HW];
__device__ float g_crcp[NB][HW];

// ---------------- helpers ----------------
__device__ __forceinline__ uint32_t bf_pack2(float v0, float v1) {
    return (uint32_t)__bfloat16_as_ushort(__float2bfloat16(v0)) |
           ((uint32_t)__bfloat16_as_ushort(__float2bfloat16(v1)) << 16);
}
__device__ __forceinline__ uint32_t hmul2u(uint32_t a, uint32_t b) {
    __nv_bfloat162 r = __hmul2(*(__nv_bfloat162*)&a, *(__nv_bfloat162*)&b);
    return *(uint32_t*)&r;
}
__device__ __forceinline__ void mma16(float* c, const uint32_t* a, const uint32_t* b) {
    asm volatile("mma.sync.aligned.m16n8k16.row.col.f32.bf16.bf16.f32 "
        "{%0,%1,%2,%3},{%4,%5,%6,%7},{%8,%9},{%0,%1,%2,%3};"
        : "+f"(c[0]), "+f"(c[1]), "+f"(c[2]), "+f"(c[3])
        : "r"(a[0]), "r"(a[1]), "r"(a[2]), "r"(a[3]), "r"(b[0]), "r"(b[1]));
}

// one BK=16 stage of bf16 mma (proven fragment mapping)
__device__ __forceinline__ void mma_block(const uint32_t* pA, const uint32_t* pB,
                                          int wm, int wn, int gid, int tig,
                                          float acc[4][4][4]) {
    uint32_t a[4][4], bb[4][2];
    #pragma unroll
    for (int mf = 0; mf < 4; mf++) {
        int m = wm + mf * 16 + gid;
        a[mf][0] = pA[tig * SMS + m];
        a[mf][1] = pA[tig * SMS + m + 8];
        a[mf][2] = pA[(tig + 4) * SMS + m];
        a[mf][3] = pA[(tig + 4) * SMS + m + 8];
    }
    #pragma unroll
    for (int nf = 0; nf < 4; nf++) {
        int n = wn + nf * 8 + gid;
        bb[nf][0] = pB[tig * SMS + n];
        bb[nf][1] = pB[(tig + 4) * SMS + n];
    }
    #pragma unroll
    for (int mf = 0; mf < 4; mf++)
        #pragma unroll
        for (int nf = 0; nf < 4; nf++)
            mma16(acc[mf][nf], a[mf], bb[nf]);
}

// ---------------------------------------------------------------------------
// k_prep (coalesced, bf16 output)
// ---------------------------------------------------------------------------
__global__ void k_prep(const float* __restrict__ fg) {
    __shared__ float t[128][33];
    __shared__ float ps[8][32];
    __shared__ float rn[32];
    int l0 = blockIdx.x * 32, b = blockIdx.y;
    int tx = threadIdx.x, ty = threadIdx.y;

    #pragma unroll
    for (int cc = ty; cc < C; cc += 8)
        t[cc][tx] = fg[((size_t)(b * C + cc)) * HW + l0 + tx] + EPSF;
    __syncthreads();

    float s = 0.f;
    #pragma unroll
    for (int cc = ty * 16; cc < ty * 16 + 16; cc++) {
        float v = t[cc][tx];
        s += v * v;
    }
    ps[ty][tx] = s;
    __syncthreads();
    if (ty == 0) {
        float tot = 0.f;
        #pragma unroll
        for (int j = 0; j < 8; j++) tot += ps[j][tx];
        rn[tx] = rsqrtf(tot);
    }
    __syncthreads();

    #pragma unroll
    for (int li = ty; li < 32; li += 8) {
        float r = rn[li];
        #pragma unroll
        for (int cc = tx; cc < C; cc += 32)
            g_k[b][l0 + li][cc] = __float2bfloat16(t[cc][li] * r);
    }
}

// ---------------------------------------------------------------------------
// y_prep (bf16 output)
// ---------------------------------------------------------------------------
__global__ void y_prep(const float* __restrict__ fg) {
    int idx = blockIdx.x * blockDim.x + threadIdx.x;
    int p = idx & (HW - 1);
    int bc = idx >> 12;
    int i = p >> 6, j = p & 63;
    const float* base = fg + (size_t)bc * HW;
    float s = 0.f;
    #pragma unroll
    for (int di = -1; di <= 1; di++) {
        int ii = i + di;
        if (ii < 0 || ii >= 64) continue;
        #pragma unroll
        for (int dj = -1; dj <= 1; dj++) {
            int jj = j + dj;
            if (jj < 0 || jj >= 64) continue;
            s += base[ii * 64 + jj];
        }
    }
    ((__nv_bfloat16*)g_y)[idx] = __float2bfloat16(s);
}

// ---------------------------------------------------------------------------
// gemm1 (bf16): acc = K.Y, then E = exp(acc - tilemax) stored bf16 + stats
// double-buffered BK=16, 8 chunks
// ---------------------------------------------------------------------------
__global__ __launch_bounds__(256) void gemm1_mma() {
    __shared__ uint32_t sh[2][2][8 * SMS];
    __shared__ float pm_sh[2][128], ps_sh[2][128], pmx_sh[128];

    int b = blockIdx.z, lt = blockIdx.y;
    int l0 = lt * 128, p0 = blockIdx.x * 128;
    int tid = threadIdx.x, wid = tid >> 5, lane = tid & 31;
    int gid = lane >> 2, tig = lane & 3;
    int wm = (wid & 1) * 64, wn = (wid >> 1) * 32;

    const __nv_bfloat16* Ag = &g_k[b][l0][0];   // rows = m (l), cols = k (c)
    const __nv_bfloat16* Bg = &g_y[b][0][p0];   // rows = k (c), cols = n (p)

    int am = tid & 127, ah4 = (tid >> 7) * 4;   // A: row am, k-pairs [ah4, ah4+4)
    int pr = tid >> 5,  bn = (tid & 31) * 4;    // B: pair-row pr, n [bn, bn+4)

    uint4 ua;
    uint2 ub0, ub1;
    ua  = *(const uint4*)(Ag + am * C + ah4 * 2);
    ub0 = *(const uint2*)(Bg + (size_t)(2 * pr) * HW + bn);
    ub1 = *(const uint2*)(Bg + (size_t)(2 * pr + 1) * HW + bn);
    {
        sh[0][0][(ah4 + 0) * SMS + am] = ua.x;
        sh[0][0][(ah4 + 1) * SMS + am] = ua.y;
        sh[0][0][(ah4 + 2) * SMS + am] = ua.z;
        sh[0][0][(ah4 + 3) * SMS + am] = ua.w;
        uint4 u;
        u.x = __byte_perm(ub0.x, ub1.x, 0x5410);
        u.y = __byte_perm(ub0.x, ub1.x, 0x7632);
        u.z = __byte_perm(ub0.y, ub1.y, 0x5410);
        u.w = __byte_perm(ub0.y, ub1.y, 0x7632);
        *(uint4*)&sh[0][1][pr * SMS + bn] = u;
    }
    __syncthreads();

    float acc[4][4][4] = {};
    for (int it = 0; it < 8; it++) {
        int st = it & 1;
        if (it < 7) {
            int c0 = (it + 1) * 16;
            ua  = *(const uint4*)(Ag + am * C + c0 + ah4 * 2);
            ub0 = *(const uint2*)(Bg + (size_t)(c0 + 2 * pr) * HW + bn);
            ub1 = *(const uint2*)(Bg + (size_t)(c0 + 2 * pr + 1) * HW + bn);
        }
        mma_block(sh[st][0], sh[st][1], wm, wn, gid, tig, acc);
        if (it < 7) {
            int ns = st ^ 1;
            sh[ns][0][(ah4 + 0) * SMS + am] = ua.x;
            sh[ns][0][(ah4 + 1) * SMS + am] = ua.y;
            sh[ns][0][(ah4 + 2) * SMS + am] = ua.z;
            sh[ns][0][(ah4 + 3) * SMS + am] = ua.w;
            uint4 u;
            u.x = __byte_perm(ub0.x, ub1.x, 0x5410);
            u.y = __byte_perm(ub0.x, ub1.x, 0x7632);
            u.z = __byte_perm(ub0.y, ub1.y, 0x5410);
            u.w = __byte_perm(ub0.y, ub1.y, 0x7632);
            *(uint4*)&sh[ns][1][pr * SMS + bn] = u;
            __syncthreads();
        }
    }

    // ---- phase 1: full column max ----
    #pragma unroll
    for (int nf = 0; nf < 4; nf++) {
        #pragma unroll
        for (int h = 0; h < 2; h++) {
            float mx = -1e30f;
            #pragma unroll
            for (int mf = 0; mf < 4; mf++)
                mx = fmaxf(mx, fmaxf(acc[mf][nf][h], acc[mf][nf][2 + h]));
            #pragma unroll
            for (int off = 4; off < 32; off <<= 1)
                mx = fmaxf(mx, __shfl_xor_sync(0xffffffffu, mx, off));
            if (gid == 0) pm_sh[wid & 1][wn + nf * 8 + 2 * tig + h] = mx;
        }
    }
    __syncthreads();
    if (tid < 128) pmx_sh[tid] = fmaxf(pm_sh[0][tid], pm_sh[1][tid]);
    __syncthreads();

    // ---- phase 2: E = exp(acc - tilemax) in-place, accumulate sums ----
    #pragma unroll
    for (int nf = 0; nf < 4; nf++) {
        #pragma unroll
        for (int h = 0; h < 2; h++) {
            int col = wn + nf * 8 + 2 * tig + h;
            float mx = pmx_sh[col];
            float sum = 0.f;
            #pragma unroll
            for (int mf = 0; mf < 4; mf++) {
                float e0 = __expf(acc[mf][nf][h] - mx);
                float e1 = __expf(acc[mf][nf][2 + h] - mx);
                acc[mf][nf][h] = e0;
                acc[mf][nf][2 + h] = e1;
                sum += e0 + e1;
            }
            #pragma unroll
            for (int off = 4; off < 32; off <<= 1)
                sum += __shfl_xor_sync(0xffffffffu, sum, off);
            if (gid == 0) ps_sh[wid & 1][col] = sum;
        }
    }
    __syncthreads();
    if (tid < 128) {
        g_pm[lt][b][p0 + tid] = pmx_sh[tid];
        g_ps[lt][b][p0 + tid] = ps_sh[0][tid] + ps_sh[1][tid];
    }

    // ---- store E tile as bf16 (pairs along p) ----
    #pragma unroll
    for (int mf = 0; mf < 4; mf++) {
        #pragma unroll
        for (int nf = 0; nf < 4; nf++) {
            int r = l0 + wm + mf * 16 + gid;
            int cc = p0 + wn + nf * 8 + 2 * tig;
            *(uint32_t*)&g_E[b][r][cc]     = bf_pack2(acc[mf][nf][0], acc[mf][nf][1]);
            *(uint32_t*)&g_E[b][r + 8][cc] = bf_pack2(acc[mf][nf][2], acc[mf][nf][3]);
        }
    }
}

// ---------------------------------------------------------------------------
// combine (proven)
// ---------------------------------------------------------------------------
__global__ void softmax_combine() {
    int idx = blockIdx.x * blockDim.x + threadIdx.x;
    int b = idx >> 12;
    int p = idx & (HW - 1);
    float m = g_pm[0][b][p];
    float s = g_ps[0][b][p];
    #pragma unroll
    for (int t = 1; t < NTILES; t++) {
        float mt = g_pm[t][b][p];
        float st = g_ps[t][b][p];
        float mn = fmaxf(m, mt);
        s = s * __expf(m - mn) + st * __expf(mt - mn);
        m = mn;
    }
    g_cmax[b][p] = m;
    g_crcp[b][p] = 1.f / s;
}

// ---------------------------------------------------------------------------
// gemm2 (bf16, split-K x4): partial[c][p] = sum_l K[l][c] * (E[l][p] * alpha)
// alpha[tile][p] = exp(pm - cmax) * rcp, updated every 8 chunks
// ---------------------------------------------------------------------------
__global__ __launch_bounds__(256) void gemm2_mma() {
    __shared__ uint32_t sh[2][2][8 * SMS];

    int b = blockIdx.y, p0 = blockIdx.x * 128, ls = blockIdx.z;
    int lbase = ls * (HW / KSPLIT);
    int tid = threadIdx.x, wid = tid >> 5, lane = tid & 31;
    int gid = lane >> 2, tig = lane & 3;
    int wm = (wid & 1) * 64, wn = (wid >> 1) * 32;

    const __nv_bfloat16* Kg = &g_k[b][0][0];   // rows = l, cols = c
    const __nv_bfloat16* Eg = &g_E[b][0][0];   // rows = l, cols = p

    int pr = tid >> 5, cn = (tid & 31) * 4;

    // per-thread column constants
    float cmx[4], crp[4];
    #pragma unroll
    for (int j = 0; j < 4; j++) {
        cmx[j] = g_cmax[b][p0 + cn + j];
        crp[j] = g_crcp[b][p0 + cn + j];
    }
    uint32_t al2[4];
    {
        int lt = lbase >> 7;
        #pragma unroll
        for (int j = 0; j < 4; j++) {
            float a = __expf(g_pm[lt][b][p0 + cn + j] - cmx[j]) * crp[j];
            al2[j] = bf_pack2(a, a);
        }
    }

    uint2 ka0, ka1, eb0, eb1;
    ka0 = *(const uint2*)(Kg + (size_t)(lbase + 2 * pr) * C + cn);
    ka1 = *(const uint2*)(Kg + (size_t)(lbase + 2 * pr + 1) * C + cn);
    eb0 = *(const uint2*)(Eg + (size_t)(lbase + 2 * pr) * HW + p0 + cn);
    eb1 = *(const uint2*)(Eg + (size_t)(lbase + 2 * pr + 1) * HW + p0 + cn);
    {
        uint4 u;
        u.x = __byte_perm(ka0.x, ka1.x, 0x5410);
        u.y = __byte_perm(ka0.x, ka1.x, 0x7632);
        u.z = __byte_perm(ka0.y, ka1.y, 0x5410);
        u.w = __byte_perm(ka0.y, ka1.y, 0x7632);
        *(uint4*)&sh[0][0][pr * SMS + cn] = u;
        u.x = hmul2u(__byte_perm(eb0.x, eb1.x, 0x5410), al2[0]);
        u.y = hmul2u(__byte_perm(eb0.x, eb1.x, 0x7632), al2[1]);
        u.z = hmul2u(__byte_perm(eb0.y, eb1.y, 0x5410), al2[2]);
        u.w = hmul2u(__byte_perm(eb0.y, eb1.y, 0x7632), al2[3]);
        *(uint4*)&sh[0][1][pr * SMS + cn] = u;
    }
    __syncthreads();

    float acc[4][4][4] = {};
    const int NIT = (HW / KSPLIT) / 16;   // 64
    for (int it = 0; it < NIT; it++) {
        int st = it & 1;
        if (it < NIT - 1) {
            int l0n = lbase + (it + 1) * 16;
            ka0 = *(const uint2*)(Kg + (size_t)(l0n + 2 * pr) * C + cn);
            ka1 = *(const uint2*)(Kg + (size_t)(l0n + 2 * pr + 1) * C + cn);
            eb0 = *(const uint2*)(Eg + (size_t)(l0n + 2 * pr) * HW + p0 + cn);
            eb1 = *(const uint2*)(Eg + (size_t)(l0n + 2 * pr + 1) * HW + p0 + cn);
            if (((it + 1) & 7) == 0) {
                int lt = l0n >> 7;
                #pragma unroll
                for (int j = 0; j < 4; j++) {
                    float a = __expf(g_pm[lt][b][p0 + cn + j] - cmx[j]) * crp[j];
                    al2[j] = bf_pack2(a, a);
                }
            }
        }
        mma_block(sh[st][0], sh[st][1], wm, wn, gid, tig, acc);
        if (it < NIT - 1) {
            int ns = st ^ 1;
            uint4 u;
            u.x = __byte_perm(ka0.x, ka1.x, 0x5410);
            u.y = __byte_perm(ka0.x, ka1.x, 0x7632);
            u.z = __byte_perm(ka0.y, ka1.y, 0x5410);
            u.w = __byte_perm(ka0.y, ka1.y, 0x7632);
            *(uint4*)&sh[ns][0][pr * SMS + cn] = u;
            u.x = hmul2u(__byte_perm(eb0.x, eb1.x, 0x5410), al2[0]);
            u.y = hmul2u(__byte_perm(eb0.x, eb1.x, 0x7632), al2[1]);
            u.z = hmul2u(__byte_perm(eb0.y, eb1.y, 0x5410), al2[2]);
            u.w = hmul2u(__byte_perm(eb0.y, eb1.y, 0x7632), al2[3]);
            *(uint4*)&sh[ns][1][pr * SMS + cn] = u;
            __syncthreads();
        }
    }

    // write partials (proven index pattern)
    float* P = &g_part[ls][b][0][0];
    #pragma unroll
    for (int mf = 0; mf < 4; mf++) {
        #pragma unroll
        for (int nf = 0; nf < 4; nf++) {
            int r = wm + mf * 16 + gid;           // c index
            int cc = p0 + wn + nf * 8 + 2 * tig;  // p index
            *(float2*)(P + (size_t)r * HW + cc)       = make_float2(acc[mf][nf][0], acc[mf][nf][1]);
            *(float2*)(P + (size_t)(r + 8) * HW + cc) = make_float2(acc[mf][nf][2], acc[mf][nf][3]);
        }
    }
}

// ---------------------------------------------------------------------------
// combine2: sum split-K partials + mask-blend epilogue (proven)
// ---------------------------------------------------------------------------
__global__ void combine2(const float* __restrict__ fg,
                         const float* __restrict__ mask,
                         float* __restrict__ out) {
    int idx = blockIdx.x * blockDim.x + threadIdx.x;   // over NB*C*HW
    int p = idx & (HW - 1);
    int b = idx >> 19;                                 // C*HW = 2^19
    int c = (idx >> 12) & (C - 1);
    float v = 0.f;
    #pragma unroll
    for (int s = 0; s < KSPLIT; s++)
        v += g_part[s][b][c][p];
    float mk = mask[b * HW + p];
    out[idx] = v * (1.f - mk) * (1.f / 9.f) + fg[idx] * mk;
}

extern "C" void kernel_launch(void* const* d_in, const int* in_sizes, int n_in,
                              void* d_out, int out_size) {
    const float* fg   = (const float*)d_in[0];
    const float* mask = (const float*)d_in[1];
    float* out = (float*)d_out;

    k_prep<<<dim3(HW / 32, NB), dim3(32, 8)>>>(fg);
    y_prep<<<(NB * C * HW) / 256, 256>>>(fg);
    gemm1_mma<<<dim3(HW / 128, HW / 128, NB), 256>>>();
    softmax_combine<<<(NB * HW) / 256, 256>>>();
    gemm2_mma<<<dim3(HW / 128, NB, KSPLIT), 256>>>();
    combine2<<<(NB * C * HW) / 256, 256>>>(fg, mask, out);
}

// round 16
// speedup vs baseline: 2.6623x; 1.0744x over previous
#include <cuda_runtime.h>
#include <cuda_bf16.h>
#include <cstdint>

#define NB 4
#define C 128
#define HW 4096
#define EPSF 1e-7f
#define NTILES (HW / 128)
#define SMS 136      // padded shared stride (uint32 units)
#define ASTR 12      // A smem row stride in uint32 (8 data + 4 pad)
#define KSPLIT 4

// ---------------- scratch ----------------
__device__ __align__(128) __nv_bfloat16 g_k[NB][HW][C];    // K[l][c] bf16
__device__ __align__(128) __nv_bfloat16 g_y[NB][C][HW];    // boxsum [c][p] bf16
__device__ __align__(128) __nv_bfloat16 g_E[NB][HW][HW];   // exp(S - tilemax) bf16
__device__ __align__(128) float g_part[KSPLIT][NB][C][HW]; // gemm2 split-K partials
__device__ float g_pm[NTILES][NB][HW];
__device__ float g_ps[NTILES][NB][HW];
__device__ float g_cmax[NB][HW];
__device__ float g_crcp[NB][HW];

// ---------------- helpers ----------------
__device__ __forceinline__ uint32_t bf_pack2(float v0, float v1) {
    return (uint32_t)__bfloat16_as_ushort(__float2bfloat16(v0)) |
           ((uint32_t)__bfloat16_as_ushort(__float2bfloat16(v1)) << 16);
}
__device__ __forceinline__ uint32_t hmul2u(uint32_t a, uint32_t b) {
    __nv_bfloat162 r = __hmul2(*(__nv_bfloat162*)&a, *(__nv_bfloat162*)&b);
    return *(uint32_t*)&r;
}
__device__ __forceinline__ void mma16(float* c, const uint32_t* a, const uint32_t* b) {
    asm volatile("mma.sync.aligned.m16n8k16.row.col.f32.bf16.bf16.f32 "
        "{%0,%1,%2,%3},{%4,%5,%6,%7},{%8,%9},{%0,%1,%2,%3};"
        : "+f"(c[0]), "+f"(c[1]), "+f"(c[2]), "+f"(c[3])
        : "r"(a[0]), "r"(a[1]), "r"(a[2]), "r"(a[3]), "r"(b[0]), "r"(b[1]));
}
__device__ __forceinline__ void ldsm_x4(uint32_t& r0, uint32_t& r1, uint32_t& r2, uint32_t& r3,
                                        uint32_t addr) {
    asm volatile("ldmatrix.sync.aligned.m8n8.x4.shared.b16 {%0,%1,%2,%3}, [%4];"
        : "=r"(r0), "=r"(r1), "=r"(r2), "=r"(r3) : "r"(addr));
}

// B-fragment-only mma stage (A comes via ldmatrix at call site) — gemm1
// B mapping proven across R8-R15.
__device__ __forceinline__ void mma_stage_ldsmA(uint32_t aSmem, const uint32_t* pB,
                                                int wm, int wn, int gid, int tig,
                                                float acc[4][4][4]) {
    uint32_t a[4][4], bb[4][2];
    #pragma unroll
    for (int mf = 0; mf < 4; mf++)
        ldsm_x4(a[mf][0], a[mf][1], a[mf][2], a[mf][3],
                aSmem + (uint32_t)((wm + mf * 16) * ASTR * 4));
    #pragma unroll
    for (int nf = 0; nf < 4; nf++) {
        int n = wn + nf * 8 + gid;
        bb[nf][0] = pB[tig * SMS + n];
        bb[nf][1] = pB[(tig + 4) * SMS + n];
    }
    #pragma unroll
    for (int mf = 0; mf < 4; mf++)
        #pragma unroll
        for (int nf = 0; nf < 4; nf++)
            mma16(acc[mf][nf], a[mf], bb[nf]);
}

// proven all-LDS stage (gemm2)
__device__ __forceinline__ void mma_block(const uint32_t* pA, const uint32_t* pB,
                                          int wm, int wn, int gid, int tig,
                                          float acc[4][4][4]) {
    uint32_t a[4][4], bb[4][2];
    #pragma unroll
    for (int mf = 0; mf < 4; mf++) {
        int m = wm + mf * 16 + gid;
        a[mf][0] = pA[tig * SMS + m];
        a[mf][1] = pA[tig * SMS + m + 8];
        a[mf][2] = pA[(tig + 4) * SMS + m];
        a[mf][3] = pA[(tig + 4) * SMS + m + 8];
    }
    #pragma unroll
    for (int nf = 0; nf < 4; nf++) {
        int n = wn + nf * 8 + gid;
        bb[nf][0] = pB[tig * SMS + n];
        bb[nf][1] = pB[(tig + 4) * SMS + n];
    }
    #pragma unroll
    for (int mf = 0; mf < 4; mf++)
        #pragma unroll
        for (int nf = 0; nf < 4; nf++)
            mma16(acc[mf][nf], a[mf], bb[nf]);
}

// ---------------------------------------------------------------------------
// k_prep (proven)
// ---------------------------------------------------------------------------
__global__ void k_prep(const float* __restrict__ fg) {
    __shared__ float t[128][33];
    __shared__ float ps[8][32];
    __shared__ float rn[32];
    int l0 = blockIdx.x * 32, b = blockIdx.y;
    int tx = threadIdx.x, ty = threadIdx.y;

    #pragma unroll
    for (int cc = ty; cc < C; cc += 8)
        t[cc][tx] = fg[((size_t)(b * C + cc)) * HW + l0 + tx] + EPSF;
    __syncthreads();

    float s = 0.f;
    #pragma unroll
    for (int cc = ty * 16; cc < ty * 16 + 16; cc++) {
        float v = t[cc][tx];
        s += v * v;
    }
    ps[ty][tx] = s;
    __syncthreads();
    if (ty == 0) {
        float tot = 0.f;
        #pragma unroll
        for (int j = 0; j < 8; j++) tot += ps[j][tx];
        rn[tx] = rsqrtf(tot);
    }
    __syncthreads();

    #pragma unroll
    for (int li = ty; li < 32; li += 8) {
        float r = rn[li];
        #pragma unroll
        for (int cc = tx; cc < C; cc += 32)
            g_k[b][l0 + li][cc] = __float2bfloat16(t[cc][li] * r);
    }
}

// ---------------------------------------------------------------------------
// y_prep (proven)
// ---------------------------------------------------------------------------
__global__ void y_prep(const float* __restrict__ fg) {
    int idx = blockIdx.x * blockDim.x + threadIdx.x;
    int p = idx & (HW - 1);
    int bc = idx >> 12;
    int i = p >> 6, j = p & 63;
    const float* base = fg + (size_t)bc * HW;
    float s = 0.f;
    #pragma unroll
    for (int di = -1; di <= 1; di++) {
        int ii = i + di;
        if (ii < 0 || ii >= 64) continue;
        #pragma unroll
        for (int dj = -1; dj <= 1; dj++) {
            int jj = j + dj;
            if (jj < 0 || jj >= 64) continue;
            s += base[ii * 64 + jj];
        }
    }
    ((__nv_bfloat16*)g_y)[idx] = __float2bfloat16(s);
}

// ---------------------------------------------------------------------------
// gemm1 (bf16, ldmatrix-A): acc = K.Y, E = exp(acc - tilemax) bf16 + stats
// A smem [m][k2] stride 12 (conflict-free); B smem proven [k2][n]
// ---------------------------------------------------------------------------
__global__ __launch_bounds__(256, 2) void gemm1_mma() {
    __shared__ uint32_t shA[2][128 * ASTR];
    __shared__ uint32_t shB[2][8 * SMS];
    __shared__ float pm_sh[2][128], ps_sh[2][128], pmx_sh[128];

    int b = blockIdx.z, lt = blockIdx.y;
    int l0 = lt * 128, p0 = blockIdx.x * 128;
    int tid = threadIdx.x, wid = tid >> 5, lane = tid & 31;
    int gid = lane >> 2, tig = lane & 3;
    int wm = (wid & 1) * 64, wn = (wid >> 1) * 32;

    const __nv_bfloat16* Ag = &g_k[b][l0][0];   // rows = m (l), cols = k (c)
    const __nv_bfloat16* Bg = &g_y[b][0][p0];   // rows = k (c), cols = n (p)

    int am = tid & 127, ah4 = (tid >> 7) * 4;   // A: row am, k-pair block ah4
    int pr = tid >> 5,  bn = (tid & 31) * 4;    // B: pair-row pr, n [bn, bn+4)

    // per-lane ldmatrix address offset: row (lane&15), k-half (lane>>4)
    uint32_t aoff = (uint32_t)(((lane & 15) * ASTR + (lane >> 4) * 4) * 4);
    uint32_t aBase0 = (uint32_t)__cvta_generic_to_shared(&shA[0][0]) + aoff;
    uint32_t aBase1 = (uint32_t)__cvta_generic_to_shared(&shA[1][0]) + aoff;

    uint4 ua;
    uint2 ub0, ub1;
    ua  = *(const uint4*)(Ag + am * C + ah4 * 2);
    ub0 = *(const uint2*)(Bg + (size_t)(2 * pr) * HW + bn);
    ub1 = *(const uint2*)(Bg + (size_t)(2 * pr + 1) * HW + bn);
    {
        *(uint4*)&shA[0][am * ASTR + ah4] = ua;
        uint4 u;
        u.x = __byte_perm(ub0.x, ub1.x, 0x5410);
        u.y = __byte_perm(ub0.x, ub1.x, 0x7632);
        u.z = __byte_perm(ub0.y, ub1.y, 0x5410);
        u.w = __byte_perm(ub0.y, ub1.y, 0x7632);
        *(uint4*)&shB[0][pr * SMS + bn] = u;
    }
    __syncthreads();

    float acc[4][4][4] = {};
    for (int it = 0; it < 8; it++) {
        int st = it & 1;
        if (it < 7) {
            int c0 = (it + 1) * 16;
            ua  = *(const uint4*)(Ag + am * C + c0 + ah4 * 2);
            ub0 = *(const uint2*)(Bg + (size_t)(c0 + 2 * pr) * HW + bn);
            ub1 = *(const uint2*)(Bg + (size_t)(c0 + 2 * pr + 1) * HW + bn);
        }
        mma_stage_ldsmA(st ? aBase1 : aBase0, shB[st], wm, wn, gid, tig, acc);
        if (it < 7) {
            int ns = st ^ 1;
            *(uint4*)&shA[ns][am * ASTR + ah4] = ua;
            uint4 u;
            u.x = __byte_perm(ub0.x, ub1.x, 0x5410);
            u.y = __byte_perm(ub0.x, ub1.x, 0x7632);
            u.z = __byte_perm(ub0.y, ub1.y, 0x5410);
            u.w = __byte_perm(ub0.y, ub1.y, 0x7632);
            *(uint4*)&shB[ns][pr * SMS + bn] = u;
            __syncthreads();
        }
    }

    // ---- phase 1: full column max (proven) ----
    #pragma unroll
    for (int nf = 0; nf < 4; nf++) {
        #pragma unroll
        for (int h = 0; h < 2; h++) {
            float mx = -1e30f;
            #pragma unroll
            for (int mf = 0; mf < 4; mf++)
                mx = fmaxf(mx, fmaxf(acc[mf][nf][h], acc[mf][nf][2 + h]));
            #pragma unroll
            for (int off = 4; off < 32; off <<= 1)
                mx = fmaxf(mx, __shfl_xor_sync(0xffffffffu, mx, off));
            if (gid == 0) pm_sh[wid & 1][wn + nf * 8 + 2 * tig + h] = mx;
        }
    }
    __syncthreads();
    if (tid < 128) pmx_sh[tid] = fmaxf(pm_sh[0][tid], pm_sh[1][tid]);
    __syncthreads();

    // ---- phase 2: E = exp(acc - tilemax) in-place + sums (proven) ----
    #pragma unroll
    for (int nf = 0; nf < 4; nf++) {
        #pragma unroll
        for (int h = 0; h < 2; h++) {
            int col = wn + nf * 8 + 2 * tig + h;
            float mx = pmx_sh[col];
            float sum = 0.f;
            #pragma unroll
            for (int mf = 0; mf < 4; mf++) {
                float e0 = __expf(acc[mf][nf][h] - mx);
                float e1 = __expf(acc[mf][nf][2 + h] - mx);
                acc[mf][nf][h] = e0;
                acc[mf][nf][2 + h] = e1;
                sum += e0 + e1;
            }
            #pragma unroll
            for (int off = 4; off < 32; off <<= 1)
                sum += __shfl_xor_sync(0xffffffffu, sum, off);
            if (gid == 0) ps_sh[wid & 1][col] = sum;
        }
    }
    __syncthreads();
    if (tid < 128) {
        g_pm[lt][b][p0 + tid] = pmx_sh[tid];
        g_ps[lt][b][p0 + tid] = ps_sh[0][tid] + ps_sh[1][tid];
    }

    // ---- store E tile as bf16 (proven) ----
    #pragma unroll
    for (int mf = 0; mf < 4; mf++) {
        #pragma unroll
        for (int nf = 0; nf < 4; nf++) {
            int r = l0 + wm + mf * 16 + gid;
            int cc = p0 + wn + nf * 8 + 2 * tig;
            *(uint32_t*)&g_E[b][r][cc]     = bf_pack2(acc[mf][nf][0], acc[mf][nf][1]);
            *(uint32_t*)&g_E[b][r + 8][cc] = bf_pack2(acc[mf][nf][2], acc[mf][nf][3]);
        }
    }
}

// ---------------------------------------------------------------------------
// combine (proven)
// ---------------------------------------------------------------------------
__global__ void softmax_combine() {
    int idx = blockIdx.x * blockDim.x + threadIdx.x;
    int b = idx >> 12;
    int p = idx & (HW - 1);
    float m = g_pm[0][b][p];
    float s = g_ps[0][b][p];
    #pragma unroll
    for (int t = 1; t < NTILES; t++) {
        float mt = g_pm[t][b][p];
        float st = g_ps[t][b][p];
        float mn = fmaxf(m, mt);
        s = s * __expf(m - mn) + st * __expf(mt - mn);
        m = mn;
    }
    g_cmax[b][p] = m;
    g_crcp[b][p] = 1.f / s;
}

// ---------------------------------------------------------------------------
// gemm2 (bf16, split-K x4, proven structure + launch_bounds)
// ---------------------------------------------------------------------------
__global__ __launch_bounds__(256, 2) void gemm2_mma() {
    __shared__ uint32_t sh[2][2][8 * SMS];

    int b = blockIdx.y, p0 = blockIdx.x * 128, ls = blockIdx.z;
    int lbase = ls * (HW / KSPLIT);
    int tid = threadIdx.x, wid = tid >> 5, lane = tid & 31;
    int gid = lane >> 2, tig = lane & 3;
    int wm = (wid & 1) * 64, wn = (wid >> 1) * 32;

    const __nv_bfloat16* Kg = &g_k[b][0][0];   // rows = l, cols = c
    const __nv_bfloat16* Eg = &g_E[b][0][0];   // rows = l, cols = p

    int pr = tid >> 5, cn = (tid & 31) * 4;

    float cmx[4], crp[4];
    #pragma unroll
    for (int j = 0; j < 4; j++) {
        cmx[j] = g_cmax[b][p0 + cn + j];
        crp[j] = g_crcp[b][p0 + cn + j];
    }
    uint32_t al2[4];
    {
        int lt = lbase >> 7;
        #pragma unroll
        for (int j = 0; j < 4; j++) {
            float a = __expf(g_pm[lt][b][p0 + cn + j] - cmx[j]) * crp[j];
            al2[j] = bf_pack2(a, a);
        }
    }

    uint2 ka0, ka1, eb0, eb1;
    ka0 = *(const uint2*)(Kg + (size_t)(lbase + 2 * pr) * C + cn);
    ka1 = *(const uint2*)(Kg + (size_t)(lbase + 2 * pr + 1) * C + cn);
    eb0 = *(const uint2*)(Eg + (size_t)(lbase + 2 * pr) * HW + p0 + cn);
    eb1 = *(const uint2*)(Eg + (size_t)(lbase + 2 * pr + 1) * HW + p0 + cn);
    {
        uint4 u;
        u.x = __byte_perm(ka0.x, ka1.x, 0x5410);
        u.y = __byte_perm(ka0.x, ka1.x, 0x7632);
        u.z = __byte_perm(ka0.y, ka1.y, 0x5410);
        u.w = __byte_perm(ka0.y, ka1.y, 0x7632);
        *(uint4*)&sh[0][0][pr * SMS + cn] = u;
        u.x = hmul2u(__byte_perm(eb0.x, eb1.x, 0x5410), al2[0]);
        u.y = hmul2u(__byte_perm(eb0.x, eb1.x, 0x7632), al2[1]);
        u.z = hmul2u(__byte_perm(eb0.y, eb1.y, 0x5410), al2[2]);
        u.w = hmul2u(__byte_perm(eb0.y, eb1.y, 0x7632), al2[3]);
        *(uint4*)&sh[0][1][pr * SMS + cn] = u;
    }
    __syncthreads();

    float acc[4][4][4] = {};
    const int NIT = (HW / KSPLIT) / 16;   // 64
    for (int it = 0; it < NIT; it++) {
        int st = it & 1;
        if (it < NIT - 1) {
            int l0n = lbase + (it + 1) * 16;
            ka0 = *(const uint2*)(Kg + (size_t)(l0n + 2 * pr) * C + cn);
            ka1 = *(const uint2*)(Kg + (size_t)(l0n + 2 * pr + 1) * C + cn);
            eb0 = *(const uint2*)(Eg + (size_t)(l0n + 2 * pr) * HW + p0 + cn);
            eb1 = *(const uint2*)(Eg + (size_t)(l0n + 2 * pr + 1) * HW + p0 + cn);
            if (((it + 1) & 7) == 0) {
                int lt = l0n >> 7;
                #pragma unroll
                for (int j = 0; j < 4; j++) {
                    float a = __expf(g_pm[lt][b][p0 + cn + j] - cmx[j]) * crp[j];
                    al2[j] = bf_pack2(a, a);
                }
            }
        }
        mma_block(sh[st][0], sh[st][1], wm, wn, gid, tig, acc);
        if (it < NIT - 1) {
            int ns = st ^ 1;
            uint4 u;
            u.x = __byte_perm(ka0.x, ka1.x, 0x5410);
            u.y = __byte_perm(ka0.x, ka1.x, 0x7632);
            u.z = __byte_perm(ka0.y, ka1.y, 0x5410);
            u.w = __byte_perm(ka0.y, ka1.y, 0x7632);
            *(uint4*)&sh[ns][0][pr * SMS + cn] = u;
            u.x = hmul2u(__byte_perm(eb0.x, eb1.x, 0x5410), al2[0]);
            u.y = hmul2u(__byte_perm(eb0.x, eb1.x, 0x7632), al2[1]);
            u.z = hmul2u(__byte_perm(eb0.y, eb1.y, 0x5410), al2[2]);
            u.w = hmul2u(__byte_perm(eb0.y, eb1.y, 0x7632), al2[3]);
            *(uint4*)&sh[ns][1][pr * SMS + cn] = u;
            __syncthreads();
        }
    }

    float* P = &g_part[ls][b][0][0];
    #pragma unroll
    for (int mf = 0; mf < 4; mf++) {
        #pragma unroll
        for (int nf = 0; nf < 4; nf++) {
            int r = wm + mf * 16 + gid;           // c index
            int cc = p0 + wn + nf * 8 + 2 * tig;  // p index
            *(float2*)(P + (size_t)r * HW + cc)       = make_float2(acc[mf][nf][0], acc[mf][nf][1]);
            *(float2*)(P + (size_t)(r + 8) * HW + cc) = make_float2(acc[mf][nf][2], acc[mf][nf][3]);
        }
    }
}

// ---------------------------------------------------------------------------
// combine2 (proven)
// ---------------------------------------------------------------------------
__global__ void combine2(const float* __restrict__ fg,
                         const float* __restrict__ mask,
                         float* __restrict__ out) {
    int idx = blockIdx.x * blockDim.x + threadIdx.x;   // over NB*C*HW
    int p = idx & (HW - 1);
    int b = idx >> 19;                                 // C*HW = 2^19
    int c = (idx >> 12) & (C - 1);
    float v = 0.f;
    #pragma unroll
    for (int s = 0; s < KSPLIT; s++)
        v += g_part[s][b][c][p];
    float mk = mask[b * HW + p];
    out[idx] = v * (1.f - mk) * (1.f / 9.f) + fg[idx] * mk;
}

extern "C" void kernel_launch(void* const* d_in, const int* in_sizes, int n_in,
                              void* d_out, int out_size) {
    const float* fg   = (const float*)d_in[0];
    const float* mask = (const float*)d_in[1];
    float* out = (float*)d_out;

    k_prep<<<dim3(HW / 32, NB), dim3(32, 8)>>>(fg);
    y_prep<<<(NB * C * HW) / 256, 256>>>(fg);
    gemm1_mma<<<dim3(HW / 128, HW / 128, NB), 256>>>();
    softmax_combine<<<(NB * HW) / 256, 256>>>();
    gemm2_mma<<<dim3(HW / 128, NB, KSPLIT), 256>>>();
    combine2<<<(NB * C * HW) / 256, 256>>>(fg, mask, out);
}

// round 17
// speedup vs baseline: 2.6645x; 1.0008x over previous
#include <cuda_runtime.h>
#include <cuda_bf16.h>
#include <cstdint>

#define NB 4
#define C 128
#define HW 4096
#define EPSF 1e-7f
#define NTILES (HW / 128)
#define ASTR 12      // gemm1 A smem row stride in uint32 (8 data + 4 pad)
#define BPAD 136     // bf16 row stride for ldmatrix tiles (17 x 16B, conflict-free)
#define KSPLIT 4

// ---------------- scratch ----------------
__device__ __align__(128) __nv_bfloat16 g_k[NB][HW][C];    // K[l][c] bf16
__device__ __align__(128) __nv_bfloat16 g_y[NB][C][HW];    // boxsum [c][p] bf16
__device__ __align__(128) __nv_bfloat16 g_E[NB][HW][HW];   // exp(S - tilemax) bf16
__device__ __align__(128) float g_part[KSPLIT][NB][C][HW]; // gemm2 split-K partials
__device__ float g_pm[NTILES][NB][HW];
__device__ float g_ps[NTILES][NB][HW];
__device__ float g_cmax[NB][HW];
__device__ float g_crcp[NB][HW];

// ---------------- helpers ----------------
__device__ __forceinline__ uint32_t bf_pack2(float v0, float v1) {
    return (uint32_t)__bfloat16_as_ushort(__float2bfloat16(v0)) |
           ((uint32_t)__bfloat16_as_ushort(__float2bfloat16(v1)) << 16);
}
__device__ __forceinline__ uint32_t hmul2u(uint32_t a, uint32_t b) {
    __nv_bfloat162 r = __hmul2(*(__nv_bfloat162*)&a, *(__nv_bfloat162*)&b);
    return *(uint32_t*)&r;
}
__device__ __forceinline__ void mma16(float* c, const uint32_t* a, const uint32_t* b) {
    asm volatile("mma.sync.aligned.m16n8k16.row.col.f32.bf16.bf16.f32 "
        "{%0,%1,%2,%3},{%4,%5,%6,%7},{%8,%9},{%0,%1,%2,%3};"
        : "+f"(c[0]), "+f"(c[1]), "+f"(c[2]), "+f"(c[3])
        : "r"(a[0]), "r"(a[1]), "r"(a[2]), "r"(a[3]), "r"(b[0]), "r"(b[1]));
}
__device__ __forceinline__ void ldsm_x4(uint32_t& r0, uint32_t& r1, uint32_t& r2, uint32_t& r3,
                                        uint32_t addr) {
    asm volatile("ldmatrix.sync.aligned.m8n8.x4.shared.b16 {%0,%1,%2,%3}, [%4];"
        : "=r"(r0), "=r"(r1), "=r"(r2), "=r"(r3) : "r"(addr));
}
__device__ __forceinline__ void ldsm_x4t(uint32_t& r0, uint32_t& r1, uint32_t& r2, uint32_t& r3,
                                         uint32_t addr) {
    asm volatile("ldmatrix.sync.aligned.m8n8.x4.trans.shared.b16 {%0,%1,%2,%3}, [%4];"
        : "=r"(r0), "=r"(r1), "=r"(r2), "=r"(r3) : "r"(addr));
}

// ---------------------------------------------------------------------------
// k_prep / y_prep (proven)
// ---------------------------------------------------------------------------
__global__ void k_prep(const float* __restrict__ fg) {
    __shared__ float t[128][33];
    __shared__ float ps[8][32];
    __shared__ float rn[32];
    int l0 = blockIdx.x * 32, b = blockIdx.y;
    int tx = threadIdx.x, ty = threadIdx.y;

    #pragma unroll
    for (int cc = ty; cc < C; cc += 8)
        t[cc][tx] = fg[((size_t)(b * C + cc)) * HW + l0 + tx] + EPSF;
    __syncthreads();

    float s = 0.f;
    #pragma unroll
    for (int cc = ty * 16; cc < ty * 16 + 16; cc++) {
        float v = t[cc][tx];
        s += v * v;
    }
    ps[ty][tx] = s;
    __syncthreads();
    if (ty == 0) {
        float tot = 0.f;
        #pragma unroll
        for (int j = 0; j < 8; j++) tot += ps[j][tx];
        rn[tx] = rsqrtf(tot);
    }
    __syncthreads();

    #pragma unroll
    for (int li = ty; li < 32; li += 8) {
        float r = rn[li];
        #pragma unroll
        for (int cc = tx; cc < C; cc += 32)
            g_k[b][l0 + li][cc] = __float2bfloat16(t[cc][li] * r);
    }
}

__global__ void y_prep(const float* __restrict__ fg) {
    int idx = blockIdx.x * blockDim.x + threadIdx.x;
    int p = idx & (HW - 1);
    int bc = idx >> 12;
    int i = p >> 6, j = p & 63;
    const float* base = fg + (size_t)bc * HW;
    float s = 0.f;
    #pragma unroll
    for (int di = -1; di <= 1; di++) {
        int ii = i + di;
        if (ii < 0 || ii >= 64) continue;
        #pragma unroll
        for (int dj = -1; dj <= 1; dj++) {
            int jj = j + dj;
            if (jj < 0 || jj >= 64) continue;
            s += base[ii * 64 + jj];
        }
    }
    ((__nv_bfloat16*)g_y)[idx] = __float2bfloat16(s);
}

// ---------------------------------------------------------------------------
// gemm1: A = K [m][k] (ldmatrix), B = Y raw [c][p] (ldmatrix.trans)
// ---------------------------------------------------------------------------
__global__ __launch_bounds__(256, 2) void gemm1_mma() {
    __shared__ uint32_t shA[2][128 * ASTR];
    __shared__ __nv_bfloat16 shY[2][16][BPAD];
    __shared__ float pm_sh[2][128], ps_sh[2][128], pmx_sh[128];

    int b = blockIdx.z, lt = blockIdx.y;
    int l0 = lt * 128, p0 = blockIdx.x * 128;
    int tid = threadIdx.x, wid = tid >> 5, lane = tid & 31;
    int gid = lane >> 2, tig = lane & 3;
    int lr = lane & 7, lg = lane >> 3;
    int wm = (wid & 1) * 64, wn = (wid >> 1) * 32;

    const __nv_bfloat16* Ag = &g_k[b][l0][0];   // rows = m (l), cols = k (c)
    const __nv_bfloat16* Bg = &g_y[b][0][p0];   // rows = k (c), cols = n (p)

    int am = tid & 127, ah4 = (tid >> 7) * 4;   // A: row am, k-uint32 block ah4
    int yr = tid >> 4,  yc8 = (tid & 15) * 8;   // Y: row yr (c), col8 (p)

    // lane offsets for ldmatrix
    uint32_t aoff = (uint32_t)(((lane & 15) * ASTR + (lane >> 4) * 4) * 4);  // A (non-trans)
    uint32_t yoff = (uint32_t)((((lg & 1) * 8 + lr) * BPAD) * 2 + (lg & 2) * 8); // trans: row k, col-half
    uint32_t aB0 = (uint32_t)__cvta_generic_to_shared(&shA[0][0]) + aoff;
    uint32_t aB1 = (uint32_t)__cvta_generic_to_shared(&shA[1][0]) + aoff;
    uint32_t yB0 = (uint32_t)__cvta_generic_to_shared(&shY[0][0][0]) + yoff;
    uint32_t yB1 = (uint32_t)__cvta_generic_to_shared(&shY[1][0][0]) + yoff;

    uint4 ua, uy;
    ua = *(const uint4*)(Ag + am * C + ah4 * 2);
    uy = *(const uint4*)(Bg + (size_t)yr * HW + yc8);
    *(uint4*)&shA[0][am * ASTR + ah4] = ua;
    *(uint4*)&shY[0][yr][yc8] = uy;
    __syncthreads();

    float acc[4][4][4] = {};
    for (int it = 0; it < 8; it++) {
        int st = it & 1;
        if (it < 7) {
            int c0 = (it + 1) * 16;
            ua = *(const uint4*)(Ag + am * C + c0 + ah4 * 2);
            uy = *(const uint4*)(Bg + (size_t)(c0 + yr) * HW + yc8);
        }
        {
            uint32_t aBase = st ? aB1 : aB0;
            uint32_t yBase = st ? yB1 : yB0;
            uint32_t a[4][4], bb[4][2];
            #pragma unroll
            for (int mf = 0; mf < 4; mf++)
                ldsm_x4(a[mf][0], a[mf][1], a[mf][2], a[mf][3],
                        aBase + (uint32_t)((wm + mf * 16) * ASTR * 4));
            #pragma unroll
            for (int nfp = 0; nfp < 2; nfp++)
                ldsm_x4t(bb[nfp * 2][0], bb[nfp * 2][1], bb[nfp * 2 + 1][0], bb[nfp * 2 + 1][1],
                         yBase + (uint32_t)((wn + nfp * 16) * 2));
            #pragma unroll
            for (int mf = 0; mf < 4; mf++)
                #pragma unroll
                for (int nf = 0; nf < 4; nf++)
                    mma16(acc[mf][nf], a[mf], bb[nf]);
        }
        if (it < 7) {
            int ns = st ^ 1;
            *(uint4*)&shA[ns][am * ASTR + ah4] = ua;
            *(uint4*)&shY[ns][yr][yc8] = uy;
            __syncthreads();
        }
    }

    // ---- phase 1: full column max (proven) ----
    #pragma unroll
    for (int nf = 0; nf < 4; nf++) {
        #pragma unroll
        for (int h = 0; h < 2; h++) {
            float mx = -1e30f;
            #pragma unroll
            for (int mf = 0; mf < 4; mf++)
                mx = fmaxf(mx, fmaxf(acc[mf][nf][h], acc[mf][nf][2 + h]));
            #pragma unroll
            for (int off = 4; off < 32; off <<= 1)
                mx = fmaxf(mx, __shfl_xor_sync(0xffffffffu, mx, off));
            if (gid == 0) pm_sh[wid & 1][wn + nf * 8 + 2 * tig + h] = mx;
        }
    }
    __syncthreads();
    if (tid < 128) pmx_sh[tid] = fmaxf(pm_sh[0][tid], pm_sh[1][tid]);
    __syncthreads();

    // ---- phase 2: E = exp(acc - tilemax) in-place + sums (proven) ----
    #pragma unroll
    for (int nf = 0; nf < 4; nf++) {
        #pragma unroll
        for (int h = 0; h < 2; h++) {
            int col = wn + nf * 8 + 2 * tig + h;
            float mx = pmx_sh[col];
            float sum = 0.f;
            #pragma unroll
            for (int mf = 0; mf < 4; mf++) {
                float e0 = __expf(acc[mf][nf][h] - mx);
                float e1 = __expf(acc[mf][nf][2 + h] - mx);
                acc[mf][nf][h] = e0;
                acc[mf][nf][2 + h] = e1;
                sum += e0 + e1;
            }
            #pragma unroll
            for (int off = 4; off < 32; off <<= 1)
                sum += __shfl_xor_sync(0xffffffffu, sum, off);
            if (gid == 0) ps_sh[wid & 1][col] = sum;
        }
    }
    __syncthreads();
    if (tid < 128) {
        g_pm[lt][b][p0 + tid] = pmx_sh[tid];
        g_ps[lt][b][p0 + tid] = ps_sh[0][tid] + ps_sh[1][tid];
    }

    // ---- store E tile as bf16 (proven) ----
    #pragma unroll
    for (int mf = 0; mf < 4; mf++) {
        #pragma unroll
        for (int nf = 0; nf < 4; nf++) {
            int r = l0 + wm + mf * 16 + gid;
            int cc = p0 + wn + nf * 8 + 2 * tig;
            *(uint32_t*)&g_E[b][r][cc]     = bf_pack2(acc[mf][nf][0], acc[mf][nf][1]);
            *(uint32_t*)&g_E[b][r + 8][cc] = bf_pack2(acc[mf][nf][2], acc[mf][nf][3]);
        }
    }
}

// ---------------------------------------------------------------------------
// combine (proven)
// ---------------------------------------------------------------------------
__global__ void softmax_combine() {
    int idx = blockIdx.x * blockDim.x + threadIdx.x;
    int b = idx >> 12;
    int p = idx & (HW - 1);
    float m = g_pm[0][b][p];
    float s = g_ps[0][b][p];
    #pragma unroll
    for (int t = 1; t < NTILES; t++) {
        float mt = g_pm[t][b][p];
        float st = g_ps[t][b][p];
        float mn = fmaxf(m, mt);
        s = s * __expf(m - mn) + st * __expf(mt - mn);
        m = mn;
    }
    g_cmax[b][p] = m;
    g_crcp[b][p] = 1.f / s;
}

// ---------------------------------------------------------------------------
// gemm2 (split-K x4): A = K raw [l][c] (trans), B = E*alpha raw [l][p] (trans)
// ---------------------------------------------------------------------------
__global__ __launch_bounds__(256, 2) void gemm2_mma() {
    __shared__ __nv_bfloat16 shK[2][16][BPAD];
    __shared__ __nv_bfloat16 shE[2][16][BPAD];

    int b = blockIdx.y, p0 = blockIdx.x * 128, ls = blockIdx.z;
    int lbase = ls * (HW / KSPLIT);
    int tid = threadIdx.x, wid = tid >> 5, lane = tid & 31;
    int gid = lane >> 2, tig = lane & 3;
    int lr = lane & 7, lg = lane >> 3;
    int wm = (wid & 1) * 64, wn = (wid >> 1) * 32;

    const __nv_bfloat16* Kg = &g_k[b][0][0];   // rows = l, cols = c
    const __nv_bfloat16* Eg = &g_E[b][0][0];   // rows = l, cols = p

    int rr = tid >> 4, c8 = (tid & 15) * 8;    // loader: row rr (l), col8 (c or p)

    // per-thread alpha for its 8 p columns (pairs along p)
    float cmx8[8], crp8[8];
    #pragma unroll
    for (int j = 0; j < 8; j++) {
        cmx8[j] = g_cmax[b][p0 + c8 + j];
        crp8[j] = g_crcp[b][p0 + c8 + j];
    }
    uint32_t al2[4];
    {
        int lt = lbase >> 7;
        #pragma unroll
        for (int j = 0; j < 4; j++) {
            float a0 = __expf(g_pm[lt][b][p0 + c8 + 2 * j]     - cmx8[2 * j])     * crp8[2 * j];
            float a1 = __expf(g_pm[lt][b][p0 + c8 + 2 * j + 1] - cmx8[2 * j + 1]) * crp8[2 * j + 1];
            al2[j] = bf_pack2(a0, a1);
        }
    }

    // trans ldmatrix lane offsets:
    // A (K): matrices (k0-7,m0-7)->r0, (k0-7,m8-15)->r1, (k8-15,m0-7)->r2, (k8-15,m8-15)->r3
    uint32_t koff = (uint32_t)((((lg & 2) * 4 + lr) * BPAD) * 2 + (lg & 1) * 16);
    // B (E): matrices (k0-7,n)->r0, (k8-15,n)->r1, (k0-7,n+8)->r2, (k8-15,n+8)->r3
    uint32_t eoff = (uint32_t)((((lg & 1) * 8 + lr) * BPAD) * 2 + (lg & 2) * 8);
    uint32_t kB0 = (uint32_t)__cvta_generic_to_shared(&shK[0][0][0]) + koff;
    uint32_t kB1 = (uint32_t)__cvta_generic_to_shared(&shK[1][0][0]) + koff;
    uint32_t eB0 = (uint32_t)__cvta_generic_to_shared(&shE[0][0][0]) + eoff;
    uint32_t eB1 = (uint32_t)__cvta_generic_to_shared(&shE[1][0][0]) + eoff;

    uint4 uk, ue;
    uk = *(const uint4*)(Kg + (size_t)(lbase + rr) * C + c8);
    ue = *(const uint4*)(Eg + (size_t)(lbase + rr) * HW + p0 + c8);
    {
        *(uint4*)&shK[0][rr][c8] = uk;
        uint4 u;
        u.x = hmul2u(ue.x, al2[0]);
        u.y = hmul2u(ue.y, al2[1]);
        u.z = hmul2u(ue.z, al2[2]);
        u.w = hmul2u(ue.w, al2[3]);
        *(uint4*)&shE[0][rr][c8] = u;
    }
    __syncthreads();

    float acc[4][4][4] = {};
    const int NIT = (HW / KSPLIT) / 16;   // 64
    for (int it = 0; it < NIT; it++) {
        int st = it & 1;
        if (it < NIT - 1) {
            int l0n = lbase + (it + 1) * 16;
            uk = *(const uint4*)(Kg + (size_t)(l0n + rr) * C + c8);
            ue = *(const uint4*)(Eg + (size_t)(l0n + rr) * HW + p0 + c8);
            if (((it + 1) & 7) == 0) {
                int lt = l0n >> 7;
                #pragma unroll
                for (int j = 0; j < 4; j++) {
                    float a0 = __expf(g_pm[lt][b][p0 + c8 + 2 * j]     - cmx8[2 * j])     * crp8[2 * j];
                    float a1 = __expf(g_pm[lt][b][p0 + c8 + 2 * j + 1] - cmx8[2 * j + 1]) * crp8[2 * j + 1];
                    al2[j] = bf_pack2(a0, a1);
                }
            }
        }
        {
            uint32_t kBase = st ? kB1 : kB0;
            uint32_t eBase = st ? eB1 : eB0;
            uint32_t a[4][4], bb[4][2];
            #pragma unroll
            for (int mf = 0; mf < 4; mf++)
                ldsm_x4t(a[mf][0], a[mf][1], a[mf][2], a[mf][3],
                         kBase + (uint32_t)((wm + mf * 16) * 2));
            #pragma unroll
            for (int nfp = 0; nfp < 2; nfp++)
                ldsm_x4t(bb[nfp * 2][0], bb[nfp * 2][1], bb[nfp * 2 + 1][0], bb[nfp * 2 + 1][1],
                         eBase + (uint32_t)((wn + nfp * 16) * 2));
            #pragma unroll
            for (int mf = 0; mf < 4; mf++)
                #pragma unroll
                for (int nf = 0; nf < 4; nf++)
                    mma16(acc[mf][nf], a[mf], bb[nf]);
        }
        if (it < NIT - 1) {
            int ns = st ^ 1;
            *(uint4*)&shK[ns][rr][c8] = uk;
            uint4 u;
            u.x = hmul2u(ue.x, al2[0]);
            u.y = hmul2u(ue.y, al2[1]);
            u.z = hmul2u(ue.z, al2[2]);
            u.w = hmul2u(ue.w, al2[3]);
            *(uint4*)&shE[ns][rr][c8] = u;
            __syncthreads();
        }
    }

    float* P = &g_part[ls][b][0][0];
    #pragma unroll
    for (int mf = 0; mf < 4; mf++) {
        #pragma unroll
        for (int nf = 0; nf < 4; nf++) {
            int r = wm + mf * 16 + gid;           // c index
            int cc = p0 + wn + nf * 8 + 2 * tig;  // p index
            *(float2*)(P + (size_t)r * HW + cc)       = make_float2(acc[mf][nf][0], acc[mf][nf][1]);
            *(float2*)(P + (size_t)(r + 8) * HW + cc) = make_float2(acc[mf][nf][2], acc[mf][nf][3]);
        }
    }
}

// ---------------------------------------------------------------------------
// combine2 (proven)
// ---------------------------------------------------------------------------
__global__ void combine2(const float* __restrict__ fg,
                         const float* __restrict__ mask,
                         float* __restrict__ out) {
    int idx = blockIdx.x * blockDim.x + threadIdx.x;   // over NB*C*HW
    int p = idx & (HW - 1);
    int b = idx >> 19;                                 // C*HW = 2^19
    int c = (idx >> 12) & (C - 1);
    float v = 0.f;
    #pragma unroll
    for (int s = 0; s < KSPLIT; s++)
        v += g_part[s][b][c][p];
    float mk = mask[b * HW + p];
    out[idx] = v * (1.f - mk) * (1.f / 9.f) + fg[idx] * mk;
}

extern "C" void kernel_launch(void* const* d_in, const int* in_sizes, int n_in,
                              void* d_out, int out_size) {
    const float* fg   = (const float*)d_in[0];
    const float* mask = (const float*)d_in[1];
    float* out = (float*)d_out;

    k_prep<<<dim3(HW / 32, NB), dim3(32, 8)>>>(fg);
    y_prep<<<(NB * C * HW) / 256, 256>>>(fg);
    gemm1_mma<<<dim3(HW / 128, HW / 128, NB), 256>>>();
    softmax_combine<<<(NB * HW) / 256, 256>>>();
    gemm2_mma<<<dim3(HW / 128, NB, KSPLIT), 256>>>();
    combine2<<<(NB * C * HW) / 256, 256>>>(fg, mask, out);
}